// round 7
// baseline (speedup 1.0000x reference)
#include <cuda_runtime.h>
#include <cuda_bf16.h>
#include <cstdint>

#define BB 2
#define NN 2048
#define MM 4096
#define DD 1024
#define HH 16
#define EE 8
#define TK 2
#define HDIM 64
#define CHUNK 512
#define ATT_SCALE 0.125f
#define SLOTS (BB * EE * NN)

#define TKK 32
#define NKT (DD / TKK)
#define ASTR 40
#define PLANE_BYTES (128 * ASTR * 2)
#define STAGE_BYTES (4 * PLANE_BYTES)
#define GEMM_SMEM   (2 * STAGE_BYTES)

// attention tiles
#define AQ 128
#define QSTR 72
#define VSTR 136
#define QPL (128 * QSTR * 2)
#define VPL (64 * VSTR * 2)
#define ATTN_SMEM (6 * QPL + 4 * VPL)   // Q(2 planes) + K(2 stages x 2) + V(2 x 2)

// ------------------------- scratch -------------------------------------------
__device__ float g_Go[(size_t)SLOTS * DD];
__device__ int   g_idx[BB * NN * TK];
__device__ float g_w[BB * NN * TK];
__device__ int   g_slot[BB * NN * TK];
__device__ int   g_qlist[BB * EE * NN];
__device__ int   g_cnt[BB * EE];
__device__ __nv_bfloat16 g_Ach[(size_t)SLOTS * DD];   // attention out (compacted)
__device__ __nv_bfloat16 g_Acl[(size_t)SLOTS * DD];
// projected planes for attention
__device__ __nv_bfloat16 g_Kbh[(size_t)BB * MM * DD];
__device__ __nv_bfloat16 g_Kbl[(size_t)BB * MM * DD];
__device__ __nv_bfloat16 g_Vth[(size_t)BB * EE * DD * CHUNK];   // [be][d][key]
__device__ __nv_bfloat16 g_Vtl[(size_t)BB * EE * DD * CHUNK];
__device__ __nv_bfloat16 g_Qph[(size_t)SLOTS * DD];   // scaled
__device__ __nv_bfloat16 g_Qpl[(size_t)SLOTS * DD];
// transposed weights [n][k]; 0=q,1=k,2=v,3=o
__device__ __nv_bfloat16 g_Wt_h[4][(size_t)EE * DD * DD];
__device__ __nv_bfloat16 g_Wt_l[4][(size_t)EE * DD * DD];

// ------------------------- PTX helpers ---------------------------------------
__device__ __forceinline__ uint32_t smem_u32p(const void* p) {
    return (uint32_t)__cvta_generic_to_shared(p);
}
__device__ __forceinline__ void cp_async16(uint32_t dst, const void* src) {
    asm volatile("cp.async.cg.shared.global [%0], [%1], 16;\n" :: "r"(dst), "l"(src));
}
__device__ __forceinline__ void cp_commit() {
    asm volatile("cp.async.commit_group;\n" ::: "memory");
}
__device__ __forceinline__ void cp_wait_all() {
    asm volatile("cp.async.wait_group 0;\n" ::: "memory");
}
template <int N>
__device__ __forceinline__ void cp_wait_group() {
    asm volatile("cp.async.wait_group %0;\n" :: "n"(N) : "memory");
}
__device__ __forceinline__ void ldsm4(uint32_t* r, uint32_t addr) {
    asm volatile("ldmatrix.sync.aligned.m8n8.x4.shared.b16 {%0,%1,%2,%3}, [%4];"
                 : "=r"(r[0]), "=r"(r[1]), "=r"(r[2]), "=r"(r[3]) : "r"(addr));
}
__device__ __forceinline__ void mma_bf16(float* d, const uint32_t* a, const uint32_t* b) {
    asm volatile(
        "mma.sync.aligned.m16n8k16.row.col.f32.bf16.bf16.f32 "
        "{%0,%1,%2,%3}, {%4,%5,%6,%7}, {%8,%9}, {%0,%1,%2,%3};"
        : "+f"(d[0]), "+f"(d[1]), "+f"(d[2]), "+f"(d[3])
        : "r"(a[0]), "r"(a[1]), "r"(a[2]), "r"(a[3]), "r"(b[0]), "r"(b[1]));
}
__device__ __forceinline__ void split_bf16(float v, __nv_bfloat16& h, __nv_bfloat16& l) {
    h = __float2bfloat16_rn(v);
    l = __float2bfloat16_rn(v - __bfloat162float(h));
}
__device__ __forceinline__ uint32_t pack_split(float x, float y, uint32_t& lo) {
    __nv_bfloat162 hi2 = __floats2bfloat162_rn(x, y);
    __nv_bfloat162 lo2 = __floats2bfloat162_rn(x - __bfloat162float(hi2.x),
                                               y - __bfloat162float(hi2.y));
    lo = *reinterpret_cast<uint32_t*>(&lo2);
    return *reinterpret_cast<uint32_t*>(&hi2);
}

// ------------------------- small kernels -------------------------------------
__global__ void zero_cnt_kernel() {
    if (threadIdx.x < BB * EE) g_cnt[threadIdx.x] = 0;
}

__global__ void router_kernel(const float* __restrict__ q,
                              const float* __restrict__ Wr,
                              const float* __restrict__ br) {
    int lane = threadIdx.x & 31;
    int qid = blockIdx.x * (blockDim.x >> 5) + (threadIdx.x >> 5);
    if (qid >= BB * NN) return;
    const float* qrow = q + (size_t)qid * DD;
    float acc[EE];
#pragma unroll
    for (int e = 0; e < EE; e++) acc[e] = 0.f;
    for (int d = lane; d < DD; d += 32) {
        float qv = qrow[d];
        const float4* w4 = reinterpret_cast<const float4*>(Wr + d * EE);
        float4 w0 = w4[0], w1 = w4[1];
        acc[0] += qv * w0.x; acc[1] += qv * w0.y;
        acc[2] += qv * w0.z; acc[3] += qv * w0.w;
        acc[4] += qv * w1.x; acc[5] += qv * w1.y;
        acc[6] += qv * w1.z; acc[7] += qv * w1.w;
    }
#pragma unroll
    for (int e = 0; e < EE; e++) {
#pragma unroll
        for (int o = 16; o > 0; o >>= 1)
            acc[e] += __shfl_xor_sync(0xffffffffu, acc[e], o);
    }
    if (lane == 0) {
        float v[EE];
#pragma unroll
        for (int e = 0; e < EE; e++) v[e] = acc[e] + br[e];
        int i0 = 0;
#pragma unroll
        for (int e = 1; e < EE; e++) if (v[e] > v[i0]) i0 = e;
        int i1 = (i0 == 0) ? 1 : 0;
#pragma unroll
        for (int e = 0; e < EE; e++) if (e != i0 && v[e] > v[i1]) i1 = e;
        float ex = __expf(v[i1] - v[i0]);
        float inv = 1.f / (1.f + ex);
        g_idx[qid * 2 + 0] = i0;
        g_idx[qid * 2 + 1] = i1;
        g_w[qid * 2 + 0] = inv;
        g_w[qid * 2 + 1] = ex * inv;
    }
}

__global__ void compact_kernel() {
    int t = blockIdx.x * blockDim.x + threadIdx.x;
    if (t >= BB * NN * TK) return;
    int qid = t >> 1;
    int b = qid / NN, n = qid % NN;
    int be = b * EE + g_idx[t];
    int pos = atomicAdd(&g_cnt[be], 1);
    g_qlist[be * NN + pos] = n;
    g_slot[t] = be * NN + pos;
}

// ------------------------- weight convert (transpose + split) ----------------
__global__ void conv_w_kernel(const float* __restrict__ Wq, const float* __restrict__ Wk,
                              const float* __restrict__ Wv, const float* __restrict__ Wo) {
    __shared__ float sm[32][33];
    int w = blockIdx.z >> 3, e = blockIdx.z & 7;
    const float* src = (w == 0 ? Wq : w == 1 ? Wk : w == 2 ? Wv : Wo) + (size_t)e * DD * DD;
    int k0 = blockIdx.x * 32, n0 = blockIdx.y * 32;
    int tid = threadIdx.x, rr = tid >> 5, cc = tid & 31;
#pragma unroll
    for (int i = 0; i < 4; i++)
        sm[rr + 8 * i][cc] = src[(size_t)(k0 + rr + 8 * i) * DD + n0 + cc];
    __syncthreads();
    __nv_bfloat16* dh = g_Wt_h[w] + (size_t)e * DD * DD;
    __nv_bfloat16* dl = g_Wt_l[w] + (size_t)e * DD * DD;
#pragma unroll
    for (int i = 0; i < 4; i++) {
        __nv_bfloat16 h, l;
        split_bf16(sm[cc][rr + 8 * i], h, l);
        size_t o = (size_t)(n0 + rr + 8 * i) * DD + k0 + cc;
        dh[o] = h; dl[o] = l;
    }
}

// ------------------------- HMMA split-bf16 GEMM core -------------------------
// C[128x128] = A[128xK]*B[128xK]^T, K-major both. 8 warps, 64x32 warp tile.
// 3-term split (Ah*Bh + Ah*Bl + Al*Bh). B planes via cp.async (2 stages).
// AFP32=1: A loaded as fp32 (optionally row-gathered) and split inline.
// MODE 0: fp32 out. 1: bf16 planes [row][DD]. 2: V-transposed planes.
// 3: bf16 planes [row][DD] scaled by ATT_SCALE.
template <int MODE, int AFP32>
__device__ __forceinline__ void gemm_body(
    const float* __restrict__ Af, const int* __restrict__ rowmap,
    const __nv_bfloat16* __restrict__ Ah, const __nv_bfloat16* __restrict__ Al,
    long rowA0,
    const __nv_bfloat16* __restrict__ Bh, const __nv_bfloat16* __restrict__ Bl, int rowB0,
    int climit, const float* __restrict__ bias, int n0,
    float* __restrict__ C, __nv_bfloat16* __restrict__ Ph, __nv_bfloat16* __restrict__ Pl,
    long crow0, size_t vtb)
{
    extern __shared__ __align__(128) char smx[];
    int tid = threadIdx.x, lane = tid & 31, warp = tid >> 5;
    uint32_t sm0 = smem_u32p(smx);

    // B loader geometry (cp.async)
    int row0 = tid >> 2, col0 = (tid & 3) * 8;
    const __nv_bfloat16* bhs = Bh + (size_t)(rowB0 + row0) * DD + col0;
    const __nv_bfloat16* bls = Bl + (size_t)(rowB0 + row0) * DD + col0;
    uint32_t soff0 = (uint32_t)(row0 * ASTR + col0) * 2;
    uint32_t soff1 = soff0 + 64 * ASTR * 2;

    // A loader geometry
    const __nv_bfloat16* ahs = nullptr; const __nv_bfloat16* als = nullptr;
    const float* afs = nullptr;
    uint32_t aoff = 0;
    float areg[16];
    if (AFP32) {
        int arow = tid >> 1, ac0 = (tid & 1) * 16;
        long r = rowmap ? (long)rowmap[min(arow, climit - 1)] : (rowA0 + arow);
        afs = Af + (size_t)r * DD + ac0;
        aoff = (uint32_t)(arow * ASTR + ac0) * 2;
    } else {
        ahs = Ah + (size_t)(rowA0 + row0) * DD + col0;
        als = Al + (size_t)(rowA0 + row0) * DD + col0;
    }

    int wr = (warp >> 2) * 64, wc = (warp & 3) * 32;
    uint32_t aRow = (uint32_t)(wr + ((lane >> 3) & 1) * 8 + (lane & 7));
    uint32_t aCol = (uint32_t)((lane >> 4) * 8);
    uint32_t bRow = (uint32_t)(wc + (lane >> 4) * 8 + (lane & 7));
    uint32_t bCol = (uint32_t)(((lane >> 3) & 1) * 8);

    float acc[4][4][4];
#pragma unroll
    for (int i = 0; i < 4; i++)
#pragma unroll
        for (int j = 0; j < 4; j++)
#pragma unroll
            for (int r = 0; r < 4; r++) acc[i][j][r] = 0.f;

    // helper: STS split A regs into stage (planes 0/1)
    auto sts_a = [&](int st) {
        __nv_bfloat16 h[16], l[16];
#pragma unroll
        for (int i = 0; i < 16; i++) split_bf16(areg[i], h[i], l[i]);
        char* base = smx + st * STAGE_BYTES;
        *reinterpret_cast<uint4*>(base + aoff)      = *reinterpret_cast<uint4*>(h);
        *reinterpret_cast<uint4*>(base + aoff + 16) = *reinterpret_cast<uint4*>(h + 8);
        *reinterpret_cast<uint4*>(base + PLANE_BYTES + aoff)      = *reinterpret_cast<uint4*>(l);
        *reinterpret_cast<uint4*>(base + PLANE_BYTES + aoff + 16) = *reinterpret_cast<uint4*>(l + 8);
    };

    // prologue: stage 0
    {
        uint32_t base = sm0;
        if (AFP32) {
#pragma unroll
            for (int j = 0; j < 4; j++)
                *reinterpret_cast<float4*>(areg + 4 * j) =
                    *reinterpret_cast<const float4*>(afs + 4 * j);
            cp_async16(base + 2 * PLANE_BYTES + soff0, bhs);
            cp_async16(base + 2 * PLANE_BYTES + soff1, bhs + (size_t)64 * DD);
            cp_async16(base + 3 * PLANE_BYTES + soff0, bls);
            cp_async16(base + 3 * PLANE_BYTES + soff1, bls + (size_t)64 * DD);
            cp_commit();
            sts_a(0);
        } else {
            cp_async16(base + 0 * PLANE_BYTES + soff0, ahs);
            cp_async16(base + 0 * PLANE_BYTES + soff1, ahs + (size_t)64 * DD);
            cp_async16(base + 1 * PLANE_BYTES + soff0, als);
            cp_async16(base + 1 * PLANE_BYTES + soff1, als + (size_t)64 * DD);
            cp_async16(base + 2 * PLANE_BYTES + soff0, bhs);
            cp_async16(base + 2 * PLANE_BYTES + soff1, bhs + (size_t)64 * DD);
            cp_async16(base + 3 * PLANE_BYTES + soff0, bls);
            cp_async16(base + 3 * PLANE_BYTES + soff1, bls + (size_t)64 * DD);
            cp_commit();
        }
    }

    for (int kt = 0; kt < NKT; kt++) {
        int st = kt & 1;
        cp_wait_all();
        __syncthreads();
        if (kt + 1 < NKT) {
            uint32_t base = sm0 + (st ^ 1) * STAGE_BYTES;
            int k0 = (kt + 1) * TKK;
            if (AFP32) {
                cp_async16(base + 2 * PLANE_BYTES + soff0, bhs + k0);
                cp_async16(base + 2 * PLANE_BYTES + soff1, bhs + (size_t)64 * DD + k0);
                cp_async16(base + 3 * PLANE_BYTES + soff0, bls + k0);
                cp_async16(base + 3 * PLANE_BYTES + soff1, bls + (size_t)64 * DD + k0);
                cp_commit();
#pragma unroll
                for (int j = 0; j < 4; j++)
                    *reinterpret_cast<float4*>(areg + 4 * j) =
                        *reinterpret_cast<const float4*>(afs + k0 + 4 * j);
            } else {
                cp_async16(base + 0 * PLANE_BYTES + soff0, ahs + k0);
                cp_async16(base + 0 * PLANE_BYTES + soff1, ahs + (size_t)64 * DD + k0);
                cp_async16(base + 1 * PLANE_BYTES + soff0, als + k0);
                cp_async16(base + 1 * PLANE_BYTES + soff1, als + (size_t)64 * DD + k0);
                cp_async16(base + 2 * PLANE_BYTES + soff0, bhs + k0);
                cp_async16(base + 2 * PLANE_BYTES + soff1, bhs + (size_t)64 * DD + k0);
                cp_async16(base + 3 * PLANE_BYTES + soff0, bls + k0);
                cp_async16(base + 3 * PLANE_BYTES + soff1, bls + (size_t)64 * DD + k0);
                cp_commit();
            }
        }
        uint32_t base = sm0 + st * STAGE_BYTES;
#pragma unroll
        for (int k16 = 0; k16 < 2; k16++) {
            uint32_t ah[4][4], al[4][4], bh[4][2], bl[4][2];
#pragma unroll
            for (int ma = 0; ma < 4; ma++) {
                uint32_t addr = base + ((aRow + ma * 16) * ASTR + k16 * 16 + aCol) * 2;
                ldsm4(ah[ma], addr);
                ldsm4(al[ma], addr + PLANE_BYTES);
            }
#pragma unroll
            for (int g = 0; g < 2; g++) {
                uint32_t addr = base + 2 * PLANE_BYTES
                              + ((bRow + g * 16) * ASTR + k16 * 16 + bCol) * 2;
                uint32_t t4[4];
                ldsm4(t4, addr);
                bh[2 * g][0] = t4[0]; bh[2 * g][1] = t4[1];
                bh[2 * g + 1][0] = t4[2]; bh[2 * g + 1][1] = t4[3];
                ldsm4(t4, addr + PLANE_BYTES);
                bl[2 * g][0] = t4[0]; bl[2 * g][1] = t4[1];
                bl[2 * g + 1][0] = t4[2]; bl[2 * g + 1][1] = t4[3];
            }
#pragma unroll
            for (int ma = 0; ma < 4; ma++)
#pragma unroll
                for (int na = 0; na < 4; na++) {
                    mma_bf16(acc[ma][na], ah[ma], bh[na]);
                    mma_bf16(acc[ma][na], ah[ma], bl[na]);
                    mma_bf16(acc[ma][na], al[ma], bh[na]);
                }
        }
        if (AFP32 && kt + 1 < NKT) sts_a(st ^ 1);
    }

    int rql = lane >> 2, cql = (lane & 3) * 2;
#pragma unroll
    for (int na = 0; na < 4; na++) {
        int colg = n0 + wc + na * 8 + cql;
        float b0 = bias[colg], b1 = bias[colg + 1];
#pragma unroll
        for (int ma = 0; ma < 4; ma++) {
#pragma unroll
            for (int hh = 0; hh < 2; hh++) {
                int rowt = wr + ma * 16 + rql + hh * 8;
                if (rowt >= climit) continue;
                float v0 = acc[ma][na][hh * 2 + 0] + b0;
                float v1 = acc[ma][na][hh * 2 + 1] + b1;
                if (MODE == 0) {
                    *reinterpret_cast<float2*>(C + (size_t)(crow0 + rowt) * DD + colg) =
                        make_float2(v0, v1);
                } else if (MODE == 1 || MODE == 3) {
                    if (MODE == 3) { v0 *= ATT_SCALE; v1 *= ATT_SCALE; }
                    uint32_t lo;
                    uint32_t hi = pack_split(v0, v1, lo);
                    size_t idx = ((size_t)(crow0 + rowt) * DD + colg) >> 1;
                    reinterpret_cast<uint32_t*>(Ph)[idx] = hi;
                    reinterpret_cast<uint32_t*>(Pl)[idx] = lo;
                } else {  // MODE 2: transposed V
                    __nv_bfloat16 h0, l0, h1, l1;
                    split_bf16(v0, h0, l0);
                    split_bf16(v1, h1, l1);
                    size_t key = (size_t)(crow0 + rowt);
                    Ph[vtb + (size_t)colg * CHUNK + key] = h0;
                    Pl[vtb + (size_t)colg * CHUNK + key] = l0;
                    Ph[vtb + (size_t)(colg + 1) * CHUNK + key] = h1;
                    Pl[vtb + (size_t)(colg + 1) * CHUNK + key] = l1;
                }
            }
        }
    }
}

__global__ __launch_bounds__(256) void kvproj_mma_kernel(
    const float* __restrict__ keys, const float* __restrict__ values,
    const float* __restrict__ bk, const float* __restrict__ bv) {
    int z = blockIdx.z;
    int which = z & 1, be = z >> 1;
    int b = be / EE, e = be % EE;
    long rowA0 = b * MM + e * CHUNK + blockIdx.y * 128;
    if (which == 0) {
        gemm_body<1, 1>(keys, nullptr, nullptr, nullptr, rowA0,
                        g_Wt_h[1], g_Wt_l[1], e * DD + blockIdx.x * 128,
                        128, bk + e * DD, blockIdx.x * 128,
                        nullptr, g_Kbh, g_Kbl, rowA0, 0);
    } else {
        gemm_body<2, 1>(values, nullptr, nullptr, nullptr, rowA0,
                        g_Wt_h[2], g_Wt_l[2], e * DD + blockIdx.x * 128,
                        128, bv + e * DD, blockIdx.x * 128,
                        nullptr, g_Vth, g_Vtl, blockIdx.y * 128, (size_t)be * DD * CHUNK);
    }
}

__global__ __launch_bounds__(256) void qproj_mma_kernel(
    const float* __restrict__ queries, const float* __restrict__ bq) {
    int be = blockIdx.z;
    int cnt = g_cnt[be];
    int m0 = blockIdx.y * 128;
    if (m0 >= cnt) return;
    int b = be / EE, e = be % EE;
    gemm_body<3, 1>(queries + (size_t)b * NN * DD, g_qlist + be * NN + m0,
                    nullptr, nullptr, 0,
                    g_Wt_h[0], g_Wt_l[0], e * DD + blockIdx.x * 128,
                    cnt - m0, bq + e * DD, blockIdx.x * 128,
                    nullptr, g_Qph, g_Qpl, be * NN + m0, 0);
}

__global__ __launch_bounds__(256) void oproj_mma_kernel(const float* __restrict__ bo) {
    int be = blockIdx.z;
    int cnt = g_cnt[be];
    int m0 = blockIdx.y * 128;
    if (m0 >= cnt) return;
    int e = be % EE;
    gemm_body<0, 0>(nullptr, nullptr, g_Ach, g_Acl, be * NN + m0,
                    g_Wt_h[3], g_Wt_l[3], e * DD + blockIdx.x * 128,
                    cnt - m0, bo + e * DD, blockIdx.x * 128,
                    g_Go, nullptr, nullptr, be * NN + m0, 0);
}

// ------------------------- HMMA flash attention (double-buffered K/V) ---------
__global__ __launch_bounds__(256, 1) void attn_mma_kernel() {
    extern __shared__ __align__(128) char smb[];
    int h = blockIdx.x, qt = blockIdx.y, be = blockIdx.z;
    int cnt = g_cnt[be];
    int q0 = qt * AQ;
    if (q0 >= cnt) return;
    int nq = min(AQ, cnt - q0);
    int b = be / EE, e = be % EE;
    int tid = threadIdx.x, lane = tid & 31, warp = tid >> 5;
    int wr = warp * 16;

    uint32_t sQ = smem_u32p(smb);
    uint32_t sK0 = sQ + 2 * QPL;
    uint32_t sV0 = sK0 + 4 * QPL;

    size_t kbase = (size_t)(b * MM + e * CHUNK) * DD + h * HDIM;
    size_t vbase = ((size_t)be * DD + h * HDIM) * CHUNK;

    auto load_kv = [&](int ktile, int stg) {
        uint32_t sKs = sK0 + stg * 2 * QPL;
        uint32_t sVs = sV0 + stg * 2 * VPL;
#pragma unroll
        for (int i = 0; i < 4; i++) {
            int cid = tid + 256 * i;
            int krow = cid >> 3, kc = (cid & 7) * 8;
            uint32_t kd = (uint32_t)(krow * QSTR + kc) * 2;
            size_t ks = kbase + (size_t)(ktile * 128 + krow) * DD + kc;
            cp_async16(sKs + kd, g_Kbh + ks);
            cp_async16(sKs + QPL + kd, g_Kbl + ks);
            int vrow = cid >> 4, vc = (cid & 15) * 8;
            uint32_t vd = (uint32_t)(vrow * VSTR + vc) * 2;
            size_t vs = vbase + (size_t)vrow * CHUNK + ktile * 128 + vc;
            cp_async16(sVs + vd, g_Vth + vs);
            cp_async16(sVs + VPL + vd, g_Vtl + vs);
        }
    };

    // prologue: Q + KV tile 0 (one group)
#pragma unroll
    for (int i = 0; i < 4; i++) {
        int cid = tid + 256 * i;
        int row = cid >> 3, c8 = (cid & 7) * 8;
        int gr = be * NN + q0 + min(row, nq - 1);
        uint32_t d = (uint32_t)(row * QSTR + c8) * 2;
        cp_async16(sQ + d, g_Qph + (size_t)gr * DD + h * HDIM + c8);
        cp_async16(sQ + QPL + d, g_Qpl + (size_t)gr * DD + h * HDIM + c8);
    }
    load_kv(0, 0);
    cp_commit();

    float oacc[8][4];
#pragma unroll
    for (int a = 0; a < 8; a++)
#pragma unroll
        for (int r = 0; r < 4; r++) oacc[a][r] = 0.f;
    float run_mx0 = -1e30f, run_mx1 = -1e30f, run_s0 = 0.f, run_s1 = 0.f;

    for (int kt = 0; kt < CHUNK / 128; kt++) {
        int stg = kt & 1;
        if (kt + 1 < CHUNK / 128) {
            load_kv(kt + 1, stg ^ 1);
            cp_commit();
            cp_wait_group<1>();
        } else {
            cp_wait_group<0>();
        }
        __syncthreads();
        uint32_t sKs = sK0 + stg * 2 * QPL;
        uint32_t sVs = sV0 + stg * 2 * VPL;

        // ---- S = Q K^T ----
        float sacc[16][4];
#pragma unroll
        for (int a = 0; a < 16; a++)
#pragma unroll
            for (int r = 0; r < 4; r++) sacc[a][r] = 0.f;

#pragma unroll
        for (int k16 = 0; k16 < 4; k16++) {
            uint32_t aH[4], aL[4];
            uint32_t aaddr = sQ + (uint32_t)((wr + ((lane >> 3) & 1) * 8 + (lane & 7)) * QSTR
                                             + k16 * 16 + (lane >> 4) * 8) * 2;
            ldsm4(aH, aaddr);
            ldsm4(aL, aaddr + QPL);
#pragma unroll
            for (int g = 0; g < 8; g++) {
                uint32_t baddr = sKs + (uint32_t)((g * 16 + (lane >> 4) * 8 + (lane & 7)) * QSTR
                                                  + k16 * 16 + ((lane >> 3) & 1) * 8) * 2;
                uint32_t tH[4], tL[4];
                ldsm4(tH, baddr);
                ldsm4(tL, baddr + QPL);
                mma_bf16(sacc[2 * g], aH, tH);
                mma_bf16(sacc[2 * g], aH, tL);
                mma_bf16(sacc[2 * g], aL, tH);
                mma_bf16(sacc[2 * g + 1], aH, tH + 2);
                mma_bf16(sacc[2 * g + 1], aH, tL + 2);
                mma_bf16(sacc[2 * g + 1], aL, tH + 2);
            }
        }

        // ---- online softmax ----
        float mx0 = -1e30f, mx1 = -1e30f;
#pragma unroll
        for (int a = 0; a < 16; a++) {
            mx0 = fmaxf(mx0, fmaxf(sacc[a][0], sacc[a][1]));
            mx1 = fmaxf(mx1, fmaxf(sacc[a][2], sacc[a][3]));
        }
        mx0 = fmaxf(mx0, __shfl_xor_sync(0xffffffffu, mx0, 1));
        mx0 = fmaxf(mx0, __shfl_xor_sync(0xffffffffu, mx0, 2));
        mx1 = fmaxf(mx1, __shfl_xor_sync(0xffffffffu, mx1, 1));
        mx1 = fmaxf(mx1, __shfl_xor_sync(0xffffffffu, mx1, 2));
        float nm0 = fmaxf(run_mx0, mx0), nm1 = fmaxf(run_mx1, mx1);
        float f0 = __expf(run_mx0 - nm0), f1 = __expf(run_mx1 - nm1);
        run_mx0 = nm0; run_mx1 = nm1;
        float s0 = 0.f, s1 = 0.f;
#pragma unroll
        for (int a = 0; a < 16; a++) {
            sacc[a][0] = __expf(sacc[a][0] - nm0); s0 += sacc[a][0];
            sacc[a][1] = __expf(sacc[a][1] - nm0); s0 += sacc[a][1];
            sacc[a][2] = __expf(sacc[a][2] - nm1); s1 += sacc[a][2];
            sacc[a][3] = __expf(sacc[a][3] - nm1); s1 += sacc[a][3];
        }
        s0 += __shfl_xor_sync(0xffffffffu, s0, 1);
        s0 += __shfl_xor_sync(0xffffffffu, s0, 2);
        s1 += __shfl_xor_sync(0xffffffffu, s1, 1);
        s1 += __shfl_xor_sync(0xffffffffu, s1, 2);
        run_s0 = run_s0 * f0 + s0;
        run_s1 = run_s1 * f1 + s1;
#pragma unroll
        for (int a = 0; a < 8; a++) {
            oacc[a][0] *= f0; oacc[a][1] *= f0;
            oacc[a][2] *= f1; oacc[a][3] *= f1;
        }

        // ---- O += P V ----
#pragma unroll
        for (int j = 0; j < 8; j++) {
            uint32_t pH[4], pL[4];
            pH[0] = pack_split(sacc[2 * j][0], sacc[2 * j][1], pL[0]);
            pH[1] = pack_split(sacc[2 * j][2], sacc[2 * j][3], pL[1]);
            pH[2] = pack_split(sacc[2 * j + 1][0], sacc[2 * j + 1][1], pL[2]);
            pH[3] = pack_split(sacc[2 * j + 1][2], sacc[2 * j + 1][3], pL[3]);
#pragma unroll
            for (int g = 0; g < 4; g++) {
                uint32_t baddr = sVs + (uint32_t)((g * 16 + (lane >> 4) * 8 + (lane & 7)) * VSTR
                                                  + j * 16 + ((lane >> 3) & 1) * 8) * 2;
                uint32_t tH[4], tL[4];
                ldsm4(tH, baddr);
                ldsm4(tL, baddr + VPL);
                mma_bf16(oacc[2 * g], pH, tH);
                mma_bf16(oacc[2 * g], pH, tL);
                mma_bf16(oacc[2 * g], pL, tH);
                mma_bf16(oacc[2 * g + 1], pH, tH + 2);
                mma_bf16(oacc[2 * g + 1], pH, tL + 2);
                mma_bf16(oacc[2 * g + 1], pL, tH + 2);
            }
        }
        __syncthreads();   // all reads of stage stg done before next prefetch reuses it
    }

    // ---- write compacted bf16 split output ----
    float inv0 = 1.f / run_s0, inv1 = 1.f / run_s1;
    int r0 = wr + (lane >> 2);
    int cql = (lane & 3) * 2;
#pragma unroll
    for (int a = 0; a < 8; a++) {
        int colg = h * HDIM + a * 8 + cql;
        if (r0 < nq) {
            uint32_t lo;
            uint32_t hi = pack_split(oacc[a][0] * inv0, oacc[a][1] * inv0, lo);
            size_t idx = ((size_t)(be * NN + q0 + r0) * DD + colg) >> 1;
            reinterpret_cast<uint32_t*>(g_Ach)[idx] = hi;
            reinterpret_cast<uint32_t*>(g_Acl)[idx] = lo;
        }
        if (r0 + 8 < nq) {
            uint32_t lo;
            uint32_t hi = pack_split(oacc[a][2] * inv1, oacc[a][3] * inv1, lo);
            size_t idx = ((size_t)(be * NN + q0 + r0 + 8) * DD + colg) >> 1;
            reinterpret_cast<uint32_t*>(g_Ach)[idx] = hi;
            reinterpret_cast<uint32_t*>(g_Acl)[idx] = lo;
        }
    }
}

// ------------------------- final combine -------------------------------------
__global__ void combine_kernel(float* __restrict__ out) {
    int t = blockIdx.x * blockDim.x + threadIdx.x;
    int qid = t >> 8;
    int d4 = (t & 255) * 4;
    float w0 = g_w[qid * 2 + 0], w1 = g_w[qid * 2 + 1];
    int s0 = g_slot[qid * 2 + 0], s1 = g_slot[qid * 2 + 1];
    float4 a = *reinterpret_cast<const float4*>(g_Go + (size_t)s0 * DD + d4);
    float4 c = *reinterpret_cast<const float4*>(g_Go + (size_t)s1 * DD + d4);
    float4 o;
    o.x = w0 * a.x + w1 * c.x;
    o.y = w0 * a.y + w1 * c.y;
    o.z = w0 * a.z + w1 * c.z;
    o.w = w0 * a.w + w1 * c.w;
    *reinterpret_cast<float4*>(out + (size_t)qid * DD + d4) = o;
}

// ------------------------- launch --------------------------------------------
extern "C" void kernel_launch(void* const* d_in, const int* in_sizes, int n_in,
                              void* d_out, int out_size) {
    const float* queries = (const float*)d_in[0];
    const float* keys    = (const float*)d_in[1];
    const float* values  = (const float*)d_in[2];
    const float* Wq = (const float*)d_in[3];
    const float* bq = (const float*)d_in[4];
    const float* Wk = (const float*)d_in[5];
    const float* bk = (const float*)d_in[6];
    const float* Wv = (const float*)d_in[7];
    const float* bv = (const float*)d_in[8];
    const float* Wo = (const float*)d_in[9];
    const float* bo = (const float*)d_in[10];
    const float* Wr = (const float*)d_in[11];
    const float* br = (const float*)d_in[12];
    float* out = (float*)d_out;
    (void)in_sizes; (void)n_in; (void)out_size;

    cudaFuncSetAttribute(kvproj_mma_kernel, cudaFuncAttributeMaxDynamicSharedMemorySize, GEMM_SMEM);
    cudaFuncSetAttribute(qproj_mma_kernel, cudaFuncAttributeMaxDynamicSharedMemorySize, GEMM_SMEM);
    cudaFuncSetAttribute(oproj_mma_kernel, cudaFuncAttributeMaxDynamicSharedMemorySize, GEMM_SMEM);
    cudaFuncSetAttribute(attn_mma_kernel, cudaFuncAttributeMaxDynamicSharedMemorySize, ATTN_SMEM);

    zero_cnt_kernel<<<1, 32>>>();
    router_kernel<<<(BB * NN) / 8, 256>>>(queries, Wr, br);
    compact_kernel<<<(BB * NN * TK) / 256, 256>>>();
    conv_w_kernel<<<dim3(32, 32, 32), 256>>>(Wq, Wk, Wv, Wo);
    kvproj_mma_kernel<<<dim3(8, 4, BB * EE * 2), 256, GEMM_SMEM>>>(keys, values, bk, bv);
    qproj_mma_kernel<<<dim3(8, 16, BB * EE), 256, GEMM_SMEM>>>(queries, bq);
    attn_mma_kernel<<<dim3(HH, NN / AQ, BB * EE), 256, ATTN_SMEM>>>();
    oproj_mma_kernel<<<dim3(8, 16, BB * EE), 256, GEMM_SMEM>>>(bo);
    combine_kernel<<<(BB * NN * DD / 4) / 256, 256>>>(out);
}

// round 8
// speedup vs baseline: 1.0437x; 1.0437x over previous
#include <cuda_runtime.h>
#include <cuda_bf16.h>
#include <cstdint>

#define BB 2
#define NN 2048
#define MM 4096
#define DD 1024
#define HH 16
#define EE 8
#define TK 2
#define HDIM 64
#define CHUNK 512
#define ATT_SCALE 0.125f
#define SLOTS (BB * EE * NN)

#define TKK 32
#define NKT (DD / TKK)
#define ASTR 40
#define PLANE_BYTES (128 * ASTR * 2)
#define STAGE_BYTES (4 * PLANE_BYTES)
#define GEMM_SMEM   (2 * STAGE_BYTES)

// attention tiles (double-buffered K/V)
#define AQ 128
#define QSTR 72
#define VSTR 136
#define QPL (128 * QSTR * 2)
#define VPL (64 * VSTR * 2)
#define ATTN_SMEM (6 * QPL + 4 * VPL)

// ------------------------- scratch -------------------------------------------
__device__ float g_Go[(size_t)SLOTS * DD];
__device__ int   g_idx[BB * NN * TK];
__device__ float g_w[BB * NN * TK];
__device__ int   g_slot[BB * NN * TK];
__device__ int   g_qlist[BB * EE * NN];
__device__ int   g_cnt[BB * EE];
// GEMM A-operand planes
__device__ __nv_bfloat16 g_Kin_h[(size_t)BB * MM * DD];
__device__ __nv_bfloat16 g_Kin_l[(size_t)BB * MM * DD];
__device__ __nv_bfloat16 g_Vin_h[(size_t)BB * MM * DD];
__device__ __nv_bfloat16 g_Vin_l[(size_t)BB * MM * DD];
__device__ __nv_bfloat16 g_Qch[(size_t)SLOTS * DD];
__device__ __nv_bfloat16 g_Qcl[(size_t)SLOTS * DD];
__device__ __nv_bfloat16 g_Ach[(size_t)SLOTS * DD];
__device__ __nv_bfloat16 g_Acl[(size_t)SLOTS * DD];
// projected planes for attention
__device__ __nv_bfloat16 g_Kbh[(size_t)BB * MM * DD];
__device__ __nv_bfloat16 g_Kbl[(size_t)BB * MM * DD];
__device__ __nv_bfloat16 g_Vth[(size_t)BB * EE * DD * CHUNK];   // [be][d][key]
__device__ __nv_bfloat16 g_Vtl[(size_t)BB * EE * DD * CHUNK];
__device__ __nv_bfloat16 g_Qph[(size_t)SLOTS * DD];   // scaled
__device__ __nv_bfloat16 g_Qpl[(size_t)SLOTS * DD];
// transposed weights [n][k]; 0=q,1=k,2=v,3=o
__device__ __nv_bfloat16 g_Wt_h[4][(size_t)EE * DD * DD];
__device__ __nv_bfloat16 g_Wt_l[4][(size_t)EE * DD * DD];

// ------------------------- PTX helpers ---------------------------------------
__device__ __forceinline__ uint32_t smem_u32p(const void* p) {
    return (uint32_t)__cvta_generic_to_shared(p);
}
__device__ __forceinline__ void cp_async16(uint32_t dst, const void* src) {
    asm volatile("cp.async.cg.shared.global [%0], [%1], 16;\n" :: "r"(dst), "l"(src));
}
__device__ __forceinline__ void cp_commit() {
    asm volatile("cp.async.commit_group;\n" ::: "memory");
}
__device__ __forceinline__ void cp_wait_all() {
    asm volatile("cp.async.wait_group 0;\n" ::: "memory");
}
template <int N>
__device__ __forceinline__ void cp_wait_group() {
    asm volatile("cp.async.wait_group %0;\n" :: "n"(N) : "memory");
}
__device__ __forceinline__ void ldsm4(uint32_t* r, uint32_t addr) {
    asm volatile("ldmatrix.sync.aligned.m8n8.x4.shared.b16 {%0,%1,%2,%3}, [%4];"
                 : "=r"(r[0]), "=r"(r[1]), "=r"(r[2]), "=r"(r[3]) : "r"(addr));
}
__device__ __forceinline__ void mma_bf16(float* d, const uint32_t* a, const uint32_t* b) {
    asm volatile(
        "mma.sync.aligned.m16n8k16.row.col.f32.bf16.bf16.f32 "
        "{%0,%1,%2,%3}, {%4,%5,%6,%7}, {%8,%9}, {%0,%1,%2,%3};"
        : "+f"(d[0]), "+f"(d[1]), "+f"(d[2]), "+f"(d[3])
        : "r"(a[0]), "r"(a[1]), "r"(a[2]), "r"(a[3]), "r"(b[0]), "r"(b[1]));
}
__device__ __forceinline__ void split_bf16(float v, __nv_bfloat16& h, __nv_bfloat16& l) {
    h = __float2bfloat16_rn(v);
    l = __float2bfloat16_rn(v - __bfloat162float(h));
}
__device__ __forceinline__ uint32_t pack_split(float x, float y, uint32_t& lo) {
    __nv_bfloat162 hi2 = __floats2bfloat162_rn(x, y);
    __nv_bfloat162 lo2 = __floats2bfloat162_rn(x - __bfloat162float(hi2.x),
                                               y - __bfloat162float(hi2.y));
    lo = *reinterpret_cast<uint32_t*>(&lo2);
    return *reinterpret_cast<uint32_t*>(&hi2);
}

// ------------------------- small kernels -------------------------------------
__global__ void zero_cnt_kernel() {
    if (threadIdx.x < BB * EE) g_cnt[threadIdx.x] = 0;
}

__global__ void router_kernel(const float* __restrict__ q,
                              const float* __restrict__ Wr,
                              const float* __restrict__ br) {
    int lane = threadIdx.x & 31;
    int qid = blockIdx.x * (blockDim.x >> 5) + (threadIdx.x >> 5);
    if (qid >= BB * NN) return;
    const float* qrow = q + (size_t)qid * DD;
    float acc[EE];
#pragma unroll
    for (int e = 0; e < EE; e++) acc[e] = 0.f;
    for (int d = lane; d < DD; d += 32) {
        float qv = qrow[d];
        const float4* w4 = reinterpret_cast<const float4*>(Wr + d * EE);
        float4 w0 = w4[0], w1 = w4[1];
        acc[0] += qv * w0.x; acc[1] += qv * w0.y;
        acc[2] += qv * w0.z; acc[3] += qv * w0.w;
        acc[4] += qv * w1.x; acc[5] += qv * w1.y;
        acc[6] += qv * w1.z; acc[7] += qv * w1.w;
    }
#pragma unroll
    for (int e = 0; e < EE; e++) {
#pragma unroll
        for (int o = 16; o > 0; o >>= 1)
            acc[e] += __shfl_xor_sync(0xffffffffu, acc[e], o);
    }
    if (lane == 0) {
        float v[EE];
#pragma unroll
        for (int e = 0; e < EE; e++) v[e] = acc[e] + br[e];
        int i0 = 0;
#pragma unroll
        for (int e = 1; e < EE; e++) if (v[e] > v[i0]) i0 = e;
        int i1 = (i0 == 0) ? 1 : 0;
#pragma unroll
        for (int e = 0; e < EE; e++) if (e != i0 && v[e] > v[i1]) i1 = e;
        float ex = __expf(v[i1] - v[i0]);
        float inv = 1.f / (1.f + ex);
        g_idx[qid * 2 + 0] = i0;
        g_idx[qid * 2 + 1] = i1;
        g_w[qid * 2 + 0] = inv;
        g_w[qid * 2 + 1] = ex * inv;
    }
}

__global__ void compact_kernel() {
    int t = blockIdx.x * blockDim.x + threadIdx.x;
    if (t >= BB * NN * TK) return;
    int qid = t >> 1;
    int b = qid / NN, n = qid % NN;
    int be = b * EE + g_idx[t];
    int pos = atomicAdd(&g_cnt[be], 1);
    g_qlist[be * NN + pos] = n;
    g_slot[t] = be * NN + pos;
}

// ------------------------- converts ------------------------------------------
// weight transpose+split: 64k x 32n tiles; writes are 128B/warp contiguous uint
__global__ void conv_w_kernel(const float* __restrict__ Wq, const float* __restrict__ Wk,
                              const float* __restrict__ Wv, const float* __restrict__ Wo) {
    __shared__ float sm[64][33];   // [k][n]
    int w = blockIdx.z >> 3, e = blockIdx.z & 7;
    const float* src = (w == 0 ? Wq : w == 1 ? Wk : w == 2 ? Wv : Wo) + (size_t)e * DD * DD;
    int k0 = blockIdx.x * 64, n0 = blockIdx.y * 32;
    int tid = threadIdx.x, rr = tid >> 5, cc = tid & 31;
#pragma unroll
    for (int i = 0; i < 8; i++)
        sm[rr + 8 * i][cc] = src[(size_t)(k0 + rr + 8 * i) * DD + n0 + cc];
    __syncthreads();
    __nv_bfloat16* dh = g_Wt_h[w] + (size_t)e * DD * DD;
    __nv_bfloat16* dl = g_Wt_l[w] + (size_t)e * DD * DD;
    int lane = tid & 31, wrow = tid >> 5;   // lane = k-pair, wrow = n row group
#pragma unroll
    for (int j = 0; j < 4; j++) {
        int n = wrow + 8 * j;
        float v0 = sm[lane * 2 + 0][n];
        float v1 = sm[lane * 2 + 1][n];
        uint32_t lo;
        uint32_t hi = pack_split(v0, v1, lo);
        size_t o = ((size_t)(n0 + n) * DD + k0 + lane * 2) >> 1;
        reinterpret_cast<uint32_t*>(dh)[o] = hi;
        reinterpret_cast<uint32_t*>(dl)[o] = lo;
    }
}

__global__ void conv_kv_kernel(const float* __restrict__ keys,
                               const float* __restrict__ values) {
    size_t n4 = (size_t)BB * MM * DD / 4;
    size_t t = (size_t)blockIdx.x * blockDim.x + threadIdx.x;
    int which = (t >= n4);
    size_t i4 = which ? (t - n4) : t;
    float4 v = reinterpret_cast<const float4*>(which ? values : keys)[i4];
    __nv_bfloat16 h[4], l[4];
    split_bf16(v.x, h[0], l[0]); split_bf16(v.y, h[1], l[1]);
    split_bf16(v.z, h[2], l[2]); split_bf16(v.w, h[3], l[3]);
    __nv_bfloat16* dh = which ? g_Vin_h : g_Kin_h;
    __nv_bfloat16* dl = which ? g_Vin_l : g_Kin_l;
    reinterpret_cast<uint2*>(dh)[i4] = *reinterpret_cast<uint2*>(h);
    reinterpret_cast<uint2*>(dl)[i4] = *reinterpret_cast<uint2*>(l);
}

__global__ void gather_split_kernel(const float* __restrict__ queries) {
    int be = blockIdx.y;
    int p = blockIdx.x * 2 + (threadIdx.x >> 7);
    if (p >= g_cnt[be]) return;
    int l128 = threadIdx.x & 127;
    int slot = be * NN + p;
    int b = be / EE;
    int n = g_qlist[be * NN + p];
    const float* src = queries + ((size_t)b * NN + n) * DD + l128 * 8;
    float4 v0 = *reinterpret_cast<const float4*>(src);
    float4 v1 = *reinterpret_cast<const float4*>(src + 4);
    __nv_bfloat16 h[8], l[8];
    split_bf16(v0.x, h[0], l[0]); split_bf16(v0.y, h[1], l[1]);
    split_bf16(v0.z, h[2], l[2]); split_bf16(v0.w, h[3], l[3]);
    split_bf16(v1.x, h[4], l[4]); split_bf16(v1.y, h[5], l[5]);
    split_bf16(v1.z, h[6], l[6]); split_bf16(v1.w, h[7], l[7]);
    __nv_bfloat16* dh = g_Qch + (size_t)slot * DD + l128 * 8;
    __nv_bfloat16* dl = g_Qcl + (size_t)slot * DD + l128 * 8;
    *reinterpret_cast<uint4*>(dh) = *reinterpret_cast<const uint4*>(h);
    *reinterpret_cast<uint4*>(dl) = *reinterpret_cast<const uint4*>(l);
}

// ------------------------- HMMA split-bf16 GEMM core (R6-proven) --------------
// MODE 0: fp32 out. 1: bf16 planes [row][DD]. 2: V-transposed planes.
// 3: bf16 planes [row][DD] scaled by ATT_SCALE.
template <int MODE>
__device__ __forceinline__ void gemm_body(
    const __nv_bfloat16* __restrict__ Ah, const __nv_bfloat16* __restrict__ Al, int rowA0,
    const __nv_bfloat16* __restrict__ Bh, const __nv_bfloat16* __restrict__ Bl, int rowB0,
    int climit, const float* __restrict__ bias, int n0,
    float* __restrict__ C, __nv_bfloat16* __restrict__ Ph, __nv_bfloat16* __restrict__ Pl,
    long crow0, size_t vtb)
{
    extern __shared__ __align__(128) char smx[];
    int tid = threadIdx.x, lane = tid & 31, warp = tid >> 5;
    uint32_t sm0 = smem_u32p(smx);

    int row0 = tid >> 2, col0 = (tid & 3) * 8;
    const __nv_bfloat16* gsrc[4];
    gsrc[0] = Ah + (size_t)(rowA0 + row0) * DD + col0;
    gsrc[1] = Al + (size_t)(rowA0 + row0) * DD + col0;
    gsrc[2] = Bh + (size_t)(rowB0 + row0) * DD + col0;
    gsrc[3] = Bl + (size_t)(rowB0 + row0) * DD + col0;
    uint32_t soff0 = (uint32_t)(row0 * ASTR + col0) * 2;
    uint32_t soff1 = soff0 + 64 * ASTR * 2;

    int wr = (warp >> 2) * 64, wc = (warp & 3) * 32;
    uint32_t aRow = (uint32_t)(wr + ((lane >> 3) & 1) * 8 + (lane & 7));
    uint32_t aCol = (uint32_t)((lane >> 4) * 8);
    uint32_t bRow = (uint32_t)(wc + (lane >> 4) * 8 + (lane & 7));
    uint32_t bCol = (uint32_t)(((lane >> 3) & 1) * 8);

    float acc[4][4][4];
#pragma unroll
    for (int i = 0; i < 4; i++)
#pragma unroll
        for (int j = 0; j < 4; j++)
#pragma unroll
            for (int r = 0; r < 4; r++) acc[i][j][r] = 0.f;

    {
        uint32_t base = sm0;
#pragma unroll
        for (int p = 0; p < 4; p++) {
            cp_async16(base + p * PLANE_BYTES + soff0, gsrc[p]);
            cp_async16(base + p * PLANE_BYTES + soff1, gsrc[p] + (size_t)64 * DD);
        }
        cp_commit();
    }

    for (int kt = 0; kt < NKT; kt++) {
        int st = kt & 1;
        cp_wait_all();
        __syncthreads();
        if (kt + 1 < NKT) {
            uint32_t base = sm0 + (st ^ 1) * STAGE_BYTES;
            int k0 = (kt + 1) * TKK;
#pragma unroll
            for (int p = 0; p < 4; p++) {
                cp_async16(base + p * PLANE_BYTES + soff0, gsrc[p] + k0);
                cp_async16(base + p * PLANE_BYTES + soff1, gsrc[p] + (size_t)64 * DD + k0);
            }
            cp_commit();
        }
        uint32_t base = sm0 + st * STAGE_BYTES;
#pragma unroll
        for (int k16 = 0; k16 < 2; k16++) {
            uint32_t ah[4][4], al[4][4], bh[4][2], bl[4][2];
#pragma unroll
            for (int ma = 0; ma < 4; ma++) {
                uint32_t addr = base + ((aRow + ma * 16) * ASTR + k16 * 16 + aCol) * 2;
                ldsm4(ah[ma], addr);
                ldsm4(al[ma], addr + PLANE_BYTES);
            }
#pragma unroll
            for (int g = 0; g < 2; g++) {
                uint32_t addr = base + 2 * PLANE_BYTES
                              + ((bRow + g * 16) * ASTR + k16 * 16 + bCol) * 2;
                uint32_t t4[4];
                ldsm4(t4, addr);
                bh[2 * g][0] = t4[0]; bh[2 * g][1] = t4[1];
                bh[2 * g + 1][0] = t4[2]; bh[2 * g + 1][1] = t4[3];
                ldsm4(t4, addr + PLANE_BYTES);
                bl[2 * g][0] = t4[0]; bl[2 * g][1] = t4[1];
                bl[2 * g + 1][0] = t4[2]; bl[2 * g + 1][1] = t4[3];
            }
#pragma unroll
            for (int ma = 0; ma < 4; ma++)
#pragma unroll
                for (int na = 0; na < 4; na++) {
                    mma_bf16(acc[ma][na], ah[ma], bh[na]);
                    mma_bf16(acc[ma][na], ah[ma], bl[na]);
                    mma_bf16(acc[ma][na], al[ma], bh[na]);
                }
        }
    }

    int rql = lane >> 2, cql = (lane & 3) * 2;
#pragma unroll
    for (int na = 0; na < 4; na++) {
        int colg = n0 + wc + na * 8 + cql;
        float b0 = bias[colg], b1 = bias[colg + 1];
#pragma unroll
        for (int ma = 0; ma < 4; ma++) {
#pragma unroll
            for (int hh = 0; hh < 2; hh++) {
                int rowt = wr + ma * 16 + rql + hh * 8;
                if (rowt >= climit) continue;
                float v0 = acc[ma][na][hh * 2 + 0] + b0;
                float v1 = acc[ma][na][hh * 2 + 1] + b1;
                if (MODE == 0) {
                    *reinterpret_cast<float2*>(C + (size_t)(crow0 + rowt) * DD + colg) =
                        make_float2(v0, v1);
                } else if (MODE == 1 || MODE == 3) {
                    if (MODE == 3) { v0 *= ATT_SCALE; v1 *= ATT_SCALE; }
                    uint32_t lo;
                    uint32_t hi = pack_split(v0, v1, lo);
                    size_t idx = ((size_t)(crow0 + rowt) * DD + colg) >> 1;
                    reinterpret_cast<uint32_t*>(Ph)[idx] = hi;
                    reinterpret_cast<uint32_t*>(Pl)[idx] = lo;
                } else {
                    __nv_bfloat16 h0, l0, h1, l1;
                    split_bf16(v0, h0, l0);
                    split_bf16(v1, h1, l1);
                    size_t key = (size_t)(crow0 + rowt);
                    Ph[vtb + (size_t)colg * CHUNK + key] = h0;
                    Pl[vtb + (size_t)colg * CHUNK + key] = l0;
                    Ph[vtb + (size_t)(colg + 1) * CHUNK + key] = h1;
                    Pl[vtb + (size_t)(colg + 1) * CHUNK + key] = l1;
                }
            }
        }
    }
}

__global__ __launch_bounds__(256) void kvproj_mma_kernel(
    const float* __restrict__ bk, const float* __restrict__ bv) {
    int z = blockIdx.z;
    int which = z & 1, be = z >> 1;
    int b = be / EE, e = be % EE;
    int rowA0 = b * MM + e * CHUNK + blockIdx.y * 128;
    if (which == 0) {
        gemm_body<1>(g_Kin_h, g_Kin_l, rowA0,
                     g_Wt_h[1], g_Wt_l[1], e * DD + blockIdx.x * 128,
                     128, bk + e * DD, blockIdx.x * 128,
                     nullptr, g_Kbh, g_Kbl, rowA0, 0);
    } else {
        gemm_body<2>(g_Vin_h, g_Vin_l, rowA0,
                     g_Wt_h[2], g_Wt_l[2], e * DD + blockIdx.x * 128,
                     128, bv + e * DD, blockIdx.x * 128,
                     nullptr, g_Vth, g_Vtl, blockIdx.y * 128, (size_t)be * DD * CHUNK);
    }
}

__global__ __launch_bounds__(256) void qproj_mma_kernel(const float* __restrict__ bq) {
    int be = blockIdx.z;
    int cnt = g_cnt[be];
    int m0 = blockIdx.y * 128;
    if (m0 >= cnt) return;
    int e = be % EE;
    gemm_body<3>(g_Qch, g_Qcl, be * NN + m0,
                 g_Wt_h[0], g_Wt_l[0], e * DD + blockIdx.x * 128,
                 cnt - m0, bq + e * DD, blockIdx.x * 128,
                 nullptr, g_Qph, g_Qpl, be * NN + m0, 0);
}

__global__ __launch_bounds__(256) void oproj_mma_kernel(const float* __restrict__ bo) {
    int be = blockIdx.z;
    int cnt = g_cnt[be];
    int m0 = blockIdx.y * 128;
    if (m0 >= cnt) return;
    int e = be % EE;
    gemm_body<0>(g_Ach, g_Acl, be * NN + m0,
                 g_Wt_h[3], g_Wt_l[3], e * DD + blockIdx.x * 128,
                 cnt - m0, bo + e * DD, blockIdx.x * 128,
                 g_Go, nullptr, nullptr, be * NN + m0, 0);
}

// ------------------------- HMMA flash attention (double-buffered K/V) ---------
__global__ __launch_bounds__(256, 1) void attn_mma_kernel() {
    extern __shared__ __align__(128) char smb[];
    int h = blockIdx.x, qt = blockIdx.y, be = blockIdx.z;
    int cnt = g_cnt[be];
    int q0 = qt * AQ;
    if (q0 >= cnt) return;
    int nq = min(AQ, cnt - q0);
    int b = be / EE, e = be % EE;
    int tid = threadIdx.x, lane = tid & 31, warp = tid >> 5;
    int wr = warp * 16;

    uint32_t sQ = smem_u32p(smb);
    uint32_t sK0 = sQ + 2 * QPL;
    uint32_t sV0 = sK0 + 4 * QPL;

    size_t kbase = (size_t)(b * MM + e * CHUNK) * DD + h * HDIM;
    size_t vbase = ((size_t)be * DD + h * HDIM) * CHUNK;

    auto load_kv = [&](int ktile, int stg) {
        uint32_t sKs = sK0 + stg * 2 * QPL;
        uint32_t sVs = sV0 + stg * 2 * VPL;
#pragma unroll
        for (int i = 0; i < 4; i++) {
            int cid = tid + 256 * i;
            int krow = cid >> 3, kc = (cid & 7) * 8;
            uint32_t kd = (uint32_t)(krow * QSTR + kc) * 2;
            size_t ks = kbase + (size_t)(ktile * 128 + krow) * DD + kc;
            cp_async16(sKs + kd, g_Kbh + ks);
            cp_async16(sKs + QPL + kd, g_Kbl + ks);
            int vrow = cid >> 4, vc = (cid & 15) * 8;
            uint32_t vd = (uint32_t)(vrow * VSTR + vc) * 2;
            size_t vs = vbase + (size_t)vrow * CHUNK + ktile * 128 + vc;
            cp_async16(sVs + vd, g_Vth + vs);
            cp_async16(sVs + VPL + vd, g_Vtl + vs);
        }
    };

#pragma unroll
    for (int i = 0; i < 4; i++) {
        int cid = tid + 256 * i;
        int row = cid >> 3, c8 = (cid & 7) * 8;
        int gr = be * NN + q0 + min(row, nq - 1);
        uint32_t d = (uint32_t)(row * QSTR + c8) * 2;
        cp_async16(sQ + d, g_Qph + (size_t)gr * DD + h * HDIM + c8);
        cp_async16(sQ + QPL + d, g_Qpl + (size_t)gr * DD + h * HDIM + c8);
    }
    load_kv(0, 0);
    cp_commit();

    float oacc[8][4];
#pragma unroll
    for (int a = 0; a < 8; a++)
#pragma unroll
        for (int r = 0; r < 4; r++) oacc[a][r] = 0.f;
    float run_mx0 = -1e30f, run_mx1 = -1e30f, run_s0 = 0.f, run_s1 = 0.f;

    for (int kt = 0; kt < CHUNK / 128; kt++) {
        int stg = kt & 1;
        if (kt + 1 < CHUNK / 128) {
            load_kv(kt + 1, stg ^ 1);
            cp_commit();
            cp_wait_group<1>();
        } else {
            cp_wait_group<0>();
        }
        __syncthreads();
        uint32_t sKs = sK0 + stg * 2 * QPL;
        uint32_t sVs = sV0 + stg * 2 * VPL;

        // ---- S = Q K^T ----
        float sacc[16][4];
#pragma unroll
        for (int a = 0; a < 16; a++)
#pragma unroll
            for (int r = 0; r < 4; r++) sacc[a][r] = 0.f;

#pragma unroll
        for (int k16 = 0; k16 < 4; k16++) {
            uint32_t aH[4], aL[4];
            uint32_t aaddr = sQ + (uint32_t)((wr + ((lane >> 3) & 1) * 8 + (lane & 7)) * QSTR
                                             + k16 * 16 + (lane >> 4) * 8) * 2;
            ldsm4(aH, aaddr);
            ldsm4(aL, aaddr + QPL);
#pragma unroll
            for (int g = 0; g < 8; g++) {
                uint32_t baddr = sKs + (uint32_t)((g * 16 + (lane >> 4) * 8 + (lane & 7)) * QSTR
                                                  + k16 * 16 + ((lane >> 3) & 1) * 8) * 2;
                uint32_t tH[4], tL[4];
                ldsm4(tH, baddr);
                ldsm4(tL, baddr + QPL);
                mma_bf16(sacc[2 * g], aH, tH);
                mma_bf16(sacc[2 * g], aH, tL);
                mma_bf16(sacc[2 * g], aL, tH);
                mma_bf16(sacc[2 * g + 1], aH, tH + 2);
                mma_bf16(sacc[2 * g + 1], aH, tL + 2);
                mma_bf16(sacc[2 * g + 1], aL, tH + 2);
            }
        }

        // ---- online softmax ----
        float mx0 = -1e30f, mx1 = -1e30f;
#pragma unroll
        for (int a = 0; a < 16; a++) {
            mx0 = fmaxf(mx0, fmaxf(sacc[a][0], sacc[a][1]));
            mx1 = fmaxf(mx1, fmaxf(sacc[a][2], sacc[a][3]));
        }
        mx0 = fmaxf(mx0, __shfl_xor_sync(0xffffffffu, mx0, 1));
        mx0 = fmaxf(mx0, __shfl_xor_sync(0xffffffffu, mx0, 2));
        mx1 = fmaxf(mx1, __shfl_xor_sync(0xffffffffu, mx1, 1));
        mx1 = fmaxf(mx1, __shfl_xor_sync(0xffffffffu, mx1, 2));
        float nm0 = fmaxf(run_mx0, mx0), nm1 = fmaxf(run_mx1, mx1);
        float f0 = __expf(run_mx0 - nm0), f1 = __expf(run_mx1 - nm1);
        run_mx0 = nm0; run_mx1 = nm1;
        float s0 = 0.f, s1 = 0.f;
#pragma unroll
        for (int a = 0; a < 16; a++) {
            sacc[a][0] = __expf(sacc[a][0] - nm0); s0 += sacc[a][0];
            sacc[a][1] = __expf(sacc[a][1] - nm0); s0 += sacc[a][1];
            sacc[a][2] = __expf(sacc[a][2] - nm1); s1 += sacc[a][2];
            sacc[a][3] = __expf(sacc[a][3] - nm1); s1 += sacc[a][3];
        }
        s0 += __shfl_xor_sync(0xffffffffu, s0, 1);
        s0 += __shfl_xor_sync(0xffffffffu, s0, 2);
        s1 += __shfl_xor_sync(0xffffffffu, s1, 1);
        s1 += __shfl_xor_sync(0xffffffffu, s1, 2);
        run_s0 = run_s0 * f0 + s0;
        run_s1 = run_s1 * f1 + s1;
#pragma unroll
        for (int a = 0; a < 8; a++) {
            oacc[a][0] *= f0; oacc[a][1] *= f0;
            oacc[a][2] *= f1; oacc[a][3] *= f1;
        }

        // ---- O += P V ----
#pragma unroll
        for (int j = 0; j < 8; j++) {
            uint32_t pH[4], pL[4];
            pH[0] = pack_split(sacc[2 * j][0], sacc[2 * j][1], pL[0]);
            pH[1] = pack_split(sacc[2 * j][2], sacc[2 * j][3], pL[1]);
            pH[2] = pack_split(sacc[2 * j + 1][0], sacc[2 * j + 1][1], pL[2]);
            pH[3] = pack_split(sacc[2 * j + 1][2], sacc[2 * j + 1][3], pL[3]);
#pragma unroll
            for (int g = 0; g < 4; g++) {
                uint32_t baddr = sVs + (uint32_t)((g * 16 + (lane >> 4) * 8 + (lane & 7)) * VSTR
                                                  + j * 16 + ((lane >> 3) & 1) * 8) * 2;
                uint32_t tH[4], tL[4];
                ldsm4(tH, baddr);
                ldsm4(tL, baddr + VPL);
                mma_bf16(oacc[2 * g], pH, tH);
                mma_bf16(oacc[2 * g], pH, tL);
                mma_bf16(oacc[2 * g], pL, tH);
                mma_bf16(oacc[2 * g + 1], pH, tH + 2);
                mma_bf16(oacc[2 * g + 1], pH, tL + 2);
                mma_bf16(oacc[2 * g + 1], pL, tH + 2);
            }
        }
        __syncthreads();
    }

    float inv0 = 1.f / run_s0, inv1 = 1.f / run_s1;
    int r0 = wr + (lane >> 2);
    int cql = (lane & 3) * 2;
#pragma unroll
    for (int a = 0; a < 8; a++) {
        int colg = h * HDIM + a * 8 + cql;
        if (r0 < nq) {
            uint32_t lo;
            uint32_t hi = pack_split(oacc[a][0] * inv0, oacc[a][1] * inv0, lo);
            size_t idx = ((size_t)(be * NN + q0 + r0) * DD + colg) >> 1;
            reinterpret_cast<uint32_t*>(g_Ach)[idx] = hi;
            reinterpret_cast<uint32_t*>(g_Acl)[idx] = lo;
        }
        if (r0 + 8 < nq) {
            uint32_t lo;
            uint32_t hi = pack_split(oacc[a][2] * inv1, oacc[a][3] * inv1, lo);
            size_t idx = ((size_t)(be * NN + q0 + r0 + 8) * DD + colg) >> 1;
            reinterpret_cast<uint32_t*>(g_Ach)[idx] = hi;
            reinterpret_cast<uint32_t*>(g_Acl)[idx] = lo;
        }
    }
}

// ------------------------- final combine -------------------------------------
__global__ void combine_kernel(float* __restrict__ out) {
    int t = blockIdx.x * blockDim.x + threadIdx.x;
    int qid = t >> 8;
    int d4 = (t & 255) * 4;
    float w0 = g_w[qid * 2 + 0], w1 = g_w[qid * 2 + 1];
    int s0 = g_slot[qid * 2 + 0], s1 = g_slot[qid * 2 + 1];
    float4 a = *reinterpret_cast<const float4*>(g_Go + (size_t)s0 * DD + d4);
    float4 c = *reinterpret_cast<const float4*>(g_Go + (size_t)s1 * DD + d4);
    float4 o;
    o.x = w0 * a.x + w1 * c.x;
    o.y = w0 * a.y + w1 * c.y;
    o.z = w0 * a.z + w1 * c.z;
    o.w = w0 * a.w + w1 * c.w;
    *reinterpret_cast<float4*>(out + (size_t)qid * DD + d4) = o;
}

// ------------------------- launch --------------------------------------------
extern "C" void kernel_launch(void* const* d_in, const int* in_sizes, int n_in,
                              void* d_out, int out_size) {
    const float* queries = (const float*)d_in[0];
    const float* keys    = (const float*)d_in[1];
    const float* values  = (const float*)d_in[2];
    const float* Wq = (const float*)d_in[3];
    const float* bq = (const float*)d_in[4];
    const float* Wk = (const float*)d_in[5];
    const float* bk = (const float*)d_in[6];
    const float* Wv = (const float*)d_in[7];
    const float* bv = (const float*)d_in[8];
    const float* Wo = (const float*)d_in[9];
    const float* bo = (const float*)d_in[10];
    const float* Wr = (const float*)d_in[11];
    const float* br = (const float*)d_in[12];
    float* out = (float*)d_out;
    (void)in_sizes; (void)n_in; (void)out_size;

    cudaFuncSetAttribute(kvproj_mma_kernel, cudaFuncAttributeMaxDynamicSharedMemorySize, GEMM_SMEM);
    cudaFuncSetAttribute(qproj_mma_kernel, cudaFuncAttributeMaxDynamicSharedMemorySize, GEMM_SMEM);
    cudaFuncSetAttribute(oproj_mma_kernel, cudaFuncAttributeMaxDynamicSharedMemorySize, GEMM_SMEM);
    cudaFuncSetAttribute(attn_mma_kernel, cudaFuncAttributeMaxDynamicSharedMemorySize, ATTN_SMEM);

    zero_cnt_kernel<<<1, 32>>>();
    router_kernel<<<(BB * NN) / 8, 256>>>(queries, Wr, br);
    compact_kernel<<<(BB * NN * TK) / 256, 256>>>();
    conv_w_kernel<<<dim3(16, 32, 32), 256>>>(Wq, Wk, Wv, Wo);
    conv_kv_kernel<<<(2 * BB * MM * DD / 4) / 256, 256>>>(keys, values);
    gather_split_kernel<<<dim3(NN / 2, BB * EE), 256>>>(queries);
    kvproj_mma_kernel<<<dim3(8, 4, BB * EE * 2), 256, GEMM_SMEM>>>(bk, bv);
    qproj_mma_kernel<<<dim3(8, 16, BB * EE), 256, GEMM_SMEM>>>(bq);
    attn_mma_kernel<<<dim3(HH, NN / AQ, BB * EE), 256, ATTN_SMEM>>>();
    oproj_mma_kernel<<<dim3(8, 16, BB * EE), 256, GEMM_SMEM>>>(bo);
    combine_kernel<<<(BB * NN * DD / 4) / 256, 256>>>(out);
}

// round 10
// speedup vs baseline: 1.4412x; 1.3809x over previous
#include <cuda_runtime.h>
#include <cuda_fp16.h>
#include <cstdint>

#define BB 2
#define NN 2048
#define MM 4096
#define DD 1024
#define HH 16
#define EE 8
#define TK 2
#define HDIM 64
#define CHUNK 512
#define ATT_SCALE 0.125f
#define SLOTS (BB * EE * NN)

#define TKK 32
#define NKT (DD / TKK)
#define ASTR 40
#define PLANE_BYTES (128 * ASTR * 2)
#define STAGE_BYTES (3 * PLANE_BYTES)   // Ah, Al, Bh
#define GEMM_SMEM   (2 * STAGE_BYTES)

// attention tiles (double-buffered K/V; V single plane)
#define AQ 128
#define QSTR 72
#define VSTR 136
#define QPL (128 * QSTR * 2)
#define VPL (64 * VSTR * 2)
#define ATTN_SMEM (6 * QPL + 2 * VPL)   // Q(2) + K(2stg x 2pl) + V(2stg x 1pl)

// ------------------------- scratch -------------------------------------------
__device__ float g_Go[(size_t)SLOTS * DD];
__device__ int   g_idx[BB * NN * TK];
__device__ float g_w[BB * NN * TK];
__device__ int   g_slot[BB * NN * TK];
__device__ int   g_qlist[BB * EE * NN];
__device__ int   g_cnt[BB * EE];
// A-operand planes (fp16 hi/lo)
__device__ __half g_Kin_h[(size_t)BB * MM * DD];
__device__ __half g_Kin_l[(size_t)BB * MM * DD];
__device__ __half g_Vin_h[(size_t)BB * MM * DD];
__device__ __half g_Vin_l[(size_t)BB * MM * DD];
__device__ __half g_Qch[(size_t)SLOTS * DD];
__device__ __half g_Qcl[(size_t)SLOTS * DD];
__device__ __half g_Ach[(size_t)SLOTS * DD];
__device__ __half g_Acl[(size_t)SLOTS * DD];
// projected planes for attention
__device__ __half g_Kbh[(size_t)BB * MM * DD];   // K proj hi
__device__ __half g_Kbl[(size_t)BB * MM * DD];   // K proj lo
__device__ __half g_Vth[(size_t)BB * EE * DD * CHUNK];   // V proj transposed, hi only
__device__ __half g_Qph[(size_t)SLOTS * DD];     // Q proj hi (scaled)
__device__ __half g_Qpl[(size_t)SLOTS * DD];     // Q proj lo
// transposed weights [n][k], hi only; 0=q,1=k,2=v,3=o
__device__ __half g_Wt_h[4][(size_t)EE * DD * DD];

// ------------------------- PTX helpers ---------------------------------------
__device__ __forceinline__ uint32_t smem_u32p(const void* p) {
    return (uint32_t)__cvta_generic_to_shared(p);
}
__device__ __forceinline__ void cp_async16(uint32_t dst, const void* src) {
    asm volatile("cp.async.cg.shared.global [%0], [%1], 16;\n" :: "r"(dst), "l"(src));
}
__device__ __forceinline__ void cp_commit() {
    asm volatile("cp.async.commit_group;\n" ::: "memory");
}
__device__ __forceinline__ void cp_wait_all() {
    asm volatile("cp.async.wait_group 0;\n" ::: "memory");
}
template <int N>
__device__ __forceinline__ void cp_wait_group() {
    asm volatile("cp.async.wait_group %0;\n" :: "n"(N) : "memory");
}
__device__ __forceinline__ void ldsm4(uint32_t* r, uint32_t addr) {
    asm volatile("ldmatrix.sync.aligned.m8n8.x4.shared.b16 {%0,%1,%2,%3}, [%4];"
                 : "=r"(r[0]), "=r"(r[1]), "=r"(r[2]), "=r"(r[3]) : "r"(addr));
}
__device__ __forceinline__ void mma_f16(float* d, const uint32_t* a, const uint32_t* b) {
    asm volatile(
        "mma.sync.aligned.m16n8k16.row.col.f32.f16.f16.f32 "
        "{%0,%1,%2,%3}, {%4,%5,%6,%7}, {%8,%9}, {%0,%1,%2,%3};"
        : "+f"(d[0]), "+f"(d[1]), "+f"(d[2]), "+f"(d[3])
        : "r"(a[0]), "r"(a[1]), "r"(a[2]), "r"(a[3]), "r"(b[0]), "r"(b[1]));
}
__device__ __forceinline__ void split_h(float v, __half& h, __half& l) {
    h = __float2half_rn(v);
    l = __float2half_rn(v - __half2float(h));
}
__device__ __forceinline__ uint32_t pack_split_h(float x, float y, uint32_t& lo) {
    __half2 h2 = __floats2half2_rn(x, y);
    __half2 l2 = __floats2half2_rn(x - __half2float(__low2half(h2)),
                                   y - __half2float(__high2half(h2)));
    lo = *reinterpret_cast<uint32_t*>(&l2);
    return *reinterpret_cast<uint32_t*>(&h2);
}

// ------------------------- small kernels -------------------------------------
__global__ void zero_cnt_kernel() {
    if (threadIdx.x < BB * EE) g_cnt[threadIdx.x] = 0;
}

__global__ void router_kernel(const float* __restrict__ q,
                              const float* __restrict__ Wr,
                              const float* __restrict__ br) {
    int lane = threadIdx.x & 31;
    int qid = blockIdx.x * (blockDim.x >> 5) + (threadIdx.x >> 5);
    if (qid >= BB * NN) return;
    const float* qrow = q + (size_t)qid * DD;
    float acc[EE];
#pragma unroll
    for (int e = 0; e < EE; e++) acc[e] = 0.f;
    for (int d = lane; d < DD; d += 32) {
        float qv = qrow[d];
        const float4* w4 = reinterpret_cast<const float4*>(Wr + d * EE);
        float4 w0 = w4[0], w1 = w4[1];
        acc[0] += qv * w0.x; acc[1] += qv * w0.y;
        acc[2] += qv * w0.z; acc[3] += qv * w0.w;
        acc[4] += qv * w1.x; acc[5] += qv * w1.y;
        acc[6] += qv * w1.z; acc[7] += qv * w1.w;
    }
#pragma unroll
    for (int e = 0; e < EE; e++) {
#pragma unroll
        for (int o = 16; o > 0; o >>= 1)
            acc[e] += __shfl_xor_sync(0xffffffffu, acc[e], o);
    }
    if (lane == 0) {
        float v[EE];
#pragma unroll
        for (int e = 0; e < EE; e++) v[e] = acc[e] + br[e];
        int i0 = 0;
#pragma unroll
        for (int e = 1; e < EE; e++) if (v[e] > v[i0]) i0 = e;
        int i1 = (i0 == 0) ? 1 : 0;
#pragma unroll
        for (int e = 0; e < EE; e++) if (e != i0 && v[e] > v[i1]) i1 = e;
        float ex = __expf(v[i1] - v[i0]);
        float inv = 1.f / (1.f + ex);
        g_idx[qid * 2 + 0] = i0;
        g_idx[qid * 2 + 1] = i1;
        g_w[qid * 2 + 0] = inv;
        g_w[qid * 2 + 1] = ex * inv;
    }
}

__global__ void compact_kernel() {
    int t = blockIdx.x * blockDim.x + threadIdx.x;
    if (t >= BB * NN * TK) return;
    int qid = t >> 1;
    int b = qid / NN, n = qid % NN;
    int be = b * EE + g_idx[t];
    int pos = atomicAdd(&g_cnt[be], 1);
    g_qlist[be * NN + pos] = n;
    g_slot[t] = be * NN + pos;
}

// ------------------------- converts ------------------------------------------
__global__ void conv_w_kernel(const float* __restrict__ Wq, const float* __restrict__ Wk,
                              const float* __restrict__ Wv, const float* __restrict__ Wo) {
    __shared__ float sm[64][33];   // [k][n]
    int w = blockIdx.z >> 3, e = blockIdx.z & 7;
    const float* src = (w == 0 ? Wq : w == 1 ? Wk : w == 2 ? Wv : Wo) + (size_t)e * DD * DD;
    int k0 = blockIdx.x * 64, n0 = blockIdx.y * 32;
    int tid = threadIdx.x, rr = tid >> 5, cc = tid & 31;
#pragma unroll
    for (int i = 0; i < 8; i++)
        sm[rr + 8 * i][cc] = src[(size_t)(k0 + rr + 8 * i) * DD + n0 + cc];
    __syncthreads();
    __half* dh = g_Wt_h[w] + (size_t)e * DD * DD;
    int lane = tid & 31, wrow = tid >> 5;
#pragma unroll
    for (int j = 0; j < 4; j++) {
        int n = wrow + 8 * j;
        __half2 h2 = __floats2half2_rn(sm[lane * 2 + 0][n], sm[lane * 2 + 1][n]);
        size_t o = ((size_t)(n0 + n) * DD + k0 + lane * 2) >> 1;
        reinterpret_cast<uint32_t*>(dh)[o] = *reinterpret_cast<uint32_t*>(&h2);
    }
}

__global__ void conv_kv_kernel(const float* __restrict__ keys,
                               const float* __restrict__ values) {
    size_t n4 = (size_t)BB * MM * DD / 4;
    size_t t = (size_t)blockIdx.x * blockDim.x + threadIdx.x;
    int which = (t >= n4);
    size_t i4 = which ? (t - n4) : t;
    float4 v = reinterpret_cast<const float4*>(which ? values : keys)[i4];
    uint32_t h[2], l[2];
    h[0] = pack_split_h(v.x, v.y, l[0]);
    h[1] = pack_split_h(v.z, v.w, l[1]);
    __half* dh = which ? g_Vin_h : g_Kin_h;
    __half* dl = which ? g_Vin_l : g_Kin_l;
    reinterpret_cast<uint2*>(dh)[i4] = *reinterpret_cast<uint2*>(h);
    reinterpret_cast<uint2*>(dl)[i4] = *reinterpret_cast<uint2*>(l);
}

__global__ void gather_split_kernel(const float* __restrict__ queries) {
    int be = blockIdx.y;
    int p = blockIdx.x * 2 + (threadIdx.x >> 7);
    if (p >= g_cnt[be]) return;
    int l128 = threadIdx.x & 127;
    int slot = be * NN + p;
    int b = be / EE;
    int n = g_qlist[be * NN + p];
    const float* src = queries + ((size_t)b * NN + n) * DD + l128 * 8;
    float4 v0 = *reinterpret_cast<const float4*>(src);
    float4 v1 = *reinterpret_cast<const float4*>(src + 4);
    uint32_t h[4], l[4];
    h[0] = pack_split_h(v0.x, v0.y, l[0]);
    h[1] = pack_split_h(v0.z, v0.w, l[1]);
    h[2] = pack_split_h(v1.x, v1.y, l[2]);
    h[3] = pack_split_h(v1.z, v1.w, l[3]);
    __half* dh = g_Qch + (size_t)slot * DD + l128 * 8;
    __half* dl = g_Qcl + (size_t)slot * DD + l128 * 8;
    *reinterpret_cast<uint4*>(dh) = *reinterpret_cast<const uint4*>(h);
    *reinterpret_cast<uint4*>(dl) = *reinterpret_cast<const uint4*>(l);
}

// ------------------------- HMMA split-fp16 GEMM core --------------------------
// C = (Ah+Al) * Bh^T : 2 MMAs per atom. A hi/lo planes, B hi plane only.
// MODE 0: fp32 out. 1: fp16 hi+lo planes [row][DD]. 2: V-transposed hi only.
// 3: fp16 hi+lo planes [row][DD] scaled by ATT_SCALE.
template <int MODE>
__device__ __forceinline__ void gemm_body(
    const __half* __restrict__ Ah, const __half* __restrict__ Al, int rowA0,
    const __half* __restrict__ Bh, int rowB0,
    int climit, const float* __restrict__ bias, int n0,
    float* __restrict__ C, __half* __restrict__ Ph, __half* __restrict__ Pl,
    long crow0, size_t vtb)
{
    extern __shared__ __align__(128) char smx[];
    int tid = threadIdx.x, lane = tid & 31, warp = tid >> 5;
    uint32_t sm0 = smem_u32p(smx);

    int row0 = tid >> 2, col0 = (tid & 3) * 8;
    const __half* gsrc[3];
    gsrc[0] = Ah + (size_t)(rowA0 + row0) * DD + col0;
    gsrc[1] = Al + (size_t)(rowA0 + row0) * DD + col0;
    gsrc[2] = Bh + (size_t)(rowB0 + row0) * DD + col0;
    uint32_t soff0 = (uint32_t)(row0 * ASTR + col0) * 2;
    uint32_t soff1 = soff0 + 64 * ASTR * 2;

    int wr = (warp >> 2) * 64, wc = (warp & 3) * 32;
    uint32_t aRow = (uint32_t)(wr + ((lane >> 3) & 1) * 8 + (lane & 7));
    uint32_t aCol = (uint32_t)((lane >> 4) * 8);
    uint32_t bRow = (uint32_t)(wc + (lane >> 4) * 8 + (lane & 7));
    uint32_t bCol = (uint32_t)(((lane >> 3) & 1) * 8);

    float acc[4][4][4];
#pragma unroll
    for (int i = 0; i < 4; i++)
#pragma unroll
        for (int j = 0; j < 4; j++)
#pragma unroll
            for (int r = 0; r < 4; r++) acc[i][j][r] = 0.f;

    {
        uint32_t base = sm0;
#pragma unroll
        for (int p = 0; p < 3; p++) {
            cp_async16(base + p * PLANE_BYTES + soff0, gsrc[p]);
            cp_async16(base + p * PLANE_BYTES + soff1, gsrc[p] + (size_t)64 * DD);
        }
        cp_commit();
    }

    for (int kt = 0; kt < NKT; kt++) {
        int st = kt & 1;
        cp_wait_all();
        __syncthreads();
        if (kt + 1 < NKT) {
            uint32_t base = sm0 + (st ^ 1) * STAGE_BYTES;
            int k0 = (kt + 1) * TKK;
#pragma unroll
            for (int p = 0; p < 3; p++) {
                cp_async16(base + p * PLANE_BYTES + soff0, gsrc[p] + k0);
                cp_async16(base + p * PLANE_BYTES + soff1, gsrc[p] + (size_t)64 * DD + k0);
            }
            cp_commit();
        }
        uint32_t base = sm0 + st * STAGE_BYTES;
#pragma unroll
        for (int k16 = 0; k16 < 2; k16++) {
            uint32_t ah[4][4], al[4][4], bh[4][2];
#pragma unroll
            for (int ma = 0; ma < 4; ma++) {
                uint32_t addr = base + ((aRow + ma * 16) * ASTR + k16 * 16 + aCol) * 2;
                ldsm4(ah[ma], addr);
                ldsm4(al[ma], addr + PLANE_BYTES);
            }
#pragma unroll
            for (int g = 0; g < 2; g++) {
                uint32_t addr = base + 2 * PLANE_BYTES
                              + ((bRow + g * 16) * ASTR + k16 * 16 + bCol) * 2;
                uint32_t t4[4];
                ldsm4(t4, addr);
                bh[2 * g][0] = t4[0]; bh[2 * g][1] = t4[1];
                bh[2 * g + 1][0] = t4[2]; bh[2 * g + 1][1] = t4[3];
            }
#pragma unroll
            for (int ma = 0; ma < 4; ma++)
#pragma unroll
                for (int na = 0; na < 4; na++) {
                    mma_f16(acc[ma][na], ah[ma], bh[na]);
                    mma_f16(acc[ma][na], al[ma], bh[na]);
                }
        }
    }

    int rql = lane >> 2, cql = (lane & 3) * 2;
#pragma unroll
    for (int na = 0; na < 4; na++) {
        int colg = n0 + wc + na * 8 + cql;
        float b0 = bias[colg], b1 = bias[colg + 1];
#pragma unroll
        for (int ma = 0; ma < 4; ma++) {
#pragma unroll
            for (int hh = 0; hh < 2; hh++) {
                int rowt = wr + ma * 16 + rql + hh * 8;
                if (rowt >= climit) continue;
                float v0 = acc[ma][na][hh * 2 + 0] + b0;
                float v1 = acc[ma][na][hh * 2 + 1] + b1;
                if (MODE == 0) {
                    *reinterpret_cast<float2*>(C + (size_t)(crow0 + rowt) * DD + colg) =
                        make_float2(v0, v1);
                } else if (MODE == 1 || MODE == 3) {
                    if (MODE == 3) { v0 *= ATT_SCALE; v1 *= ATT_SCALE; }
                    uint32_t lo;
                    uint32_t hi = pack_split_h(v0, v1, lo);
                    size_t idx = ((size_t)(crow0 + rowt) * DD + colg) >> 1;
                    reinterpret_cast<uint32_t*>(Ph)[idx] = hi;
                    reinterpret_cast<uint32_t*>(Pl)[idx] = lo;
                } else {  // MODE 2: transposed V, hi only
                    size_t key = (size_t)(crow0 + rowt);
                    Ph[vtb + (size_t)colg * CHUNK + key] = __float2half_rn(v0);
                    Ph[vtb + (size_t)(colg + 1) * CHUNK + key] = __float2half_rn(v1);
                }
            }
        }
    }
}

__global__ __launch_bounds__(256) void kvproj_mma_kernel(
    const float* __restrict__ bk, const float* __restrict__ bv) {
    int z = blockIdx.z;
    int which = z & 1, be = z >> 1;
    int b = be / EE, e = be % EE;
    int rowA0 = b * MM + e * CHUNK + blockIdx.y * 128;
    if (which == 0) {
        gemm_body<1>(g_Kin_h, g_Kin_l, rowA0,
                     g_Wt_h[1], e * DD + blockIdx.x * 128,
                     128, bk + e * DD, blockIdx.x * 128,
                     nullptr, g_Kbh, g_Kbl, rowA0, 0);
    } else {
        gemm_body<2>(g_Vin_h, g_Vin_l, rowA0,
                     g_Wt_h[2], e * DD + blockIdx.x * 128,
                     128, bv + e * DD, blockIdx.x * 128,
                     nullptr, g_Vth, nullptr, blockIdx.y * 128, (size_t)be * DD * CHUNK);
    }
}

__global__ __launch_bounds__(256) void qproj_mma_kernel(const float* __restrict__ bq) {
    int be = blockIdx.z;
    int cnt = g_cnt[be];
    int m0 = blockIdx.y * 128;
    if (m0 >= cnt) return;
    int e = be % EE;
    gemm_body<3>(g_Qch, g_Qcl, be * NN + m0,
                 g_Wt_h[0], e * DD + blockIdx.x * 128,
                 cnt - m0, bq + e * DD, blockIdx.x * 128,
                 nullptr, g_Qph, g_Qpl, be * NN + m0, 0);
}

__global__ __launch_bounds__(256) void oproj_mma_kernel(const float* __restrict__ bo) {
    int be = blockIdx.z;
    int cnt = g_cnt[be];
    int m0 = blockIdx.y * 128;
    if (m0 >= cnt) return;
    int e = be % EE;
    gemm_body<0>(g_Ach, g_Acl, be * NN + m0,
                 g_Wt_h[3], e * DD + blockIdx.x * 128,
                 cnt - m0, bo + e * DD, blockIdx.x * 128,
                 g_Go, nullptr, nullptr, be * NN + m0, 0);
}

// ------------------------- HMMA flash attention -------------------------------
// QK: 3-term (Q hi+lo x K hi+lo, drop lo*lo). PV: P hi+lo x V hi (2-term).
__global__ __launch_bounds__(256, 1) void attn_mma_kernel() {
    extern __shared__ __align__(128) char smb[];
    int h = blockIdx.x, qt = blockIdx.y, be = blockIdx.z;
    int cnt = g_cnt[be];
    int q0 = qt * AQ;
    if (q0 >= cnt) return;
    int nq = min(AQ, cnt - q0);
    int b = be / EE, e = be % EE;
    int tid = threadIdx.x, lane = tid & 31, warp = tid >> 5;
    int wr = warp * 16;

    uint32_t sQ = smem_u32p(smb);
    uint32_t sK0 = sQ + 2 * QPL;
    uint32_t sV0 = sK0 + 4 * QPL;

    size_t kbase = (size_t)(b * MM + e * CHUNK) * DD + h * HDIM;
    size_t vbase = ((size_t)be * DD + h * HDIM) * CHUNK;

    auto load_kv = [&](int ktile, int stg) {
        uint32_t sKs = sK0 + stg * 2 * QPL;
        uint32_t sVs = sV0 + stg * VPL;
#pragma unroll
        for (int i = 0; i < 4; i++) {
            int cid = tid + 256 * i;
            int krow = cid >> 3, kc = (cid & 7) * 8;
            uint32_t kd = (uint32_t)(krow * QSTR + kc) * 2;
            size_t ks = kbase + (size_t)(ktile * 128 + krow) * DD + kc;
            cp_async16(sKs + kd, g_Kbh + ks);
            cp_async16(sKs + QPL + kd, g_Kbl + ks);
            // V hi plane: 64 d-rows x 16 chunks = 1024 chunks (full i<4 range)
            int vrow = cid >> 4, vc = (cid & 15) * 8;
            uint32_t vd = (uint32_t)(vrow * VSTR + vc) * 2;
            size_t vs = vbase + (size_t)vrow * CHUNK + ktile * 128 + vc;
            if (i < 4) cp_async16(sVs + vd, g_Vth + vs);
        }
    };

#pragma unroll
    for (int i = 0; i < 4; i++) {
        int cid = tid + 256 * i;
        int row = cid >> 3, c8 = (cid & 7) * 8;
        int gr = be * NN + q0 + min(row, nq - 1);
        uint32_t d = (uint32_t)(row * QSTR + c8) * 2;
        cp_async16(sQ + d, g_Qph + (size_t)gr * DD + h * HDIM + c8);
        cp_async16(sQ + QPL + d, g_Qpl + (size_t)gr * DD + h * HDIM + c8);
    }
    load_kv(0, 0);
    cp_commit();

    float oacc[8][4];
#pragma unroll
    for (int a = 0; a < 8; a++)
#pragma unroll
        for (int r = 0; r < 4; r++) oacc[a][r] = 0.f;
    float run_mx0 = -1e30f, run_mx1 = -1e30f, run_s0 = 0.f, run_s1 = 0.f;

    for (int kt = 0; kt < CHUNK / 128; kt++) {
        int stg = kt & 1;
        if (kt + 1 < CHUNK / 128) {
            load_kv(kt + 1, stg ^ 1);
            cp_commit();
            cp_wait_group<1>();
        } else {
            cp_wait_group<0>();
        }
        __syncthreads();
        uint32_t sKs = sK0 + stg * 2 * QPL;
        uint32_t sVs = sV0 + stg * VPL;

        // ---- S = Q K^T (3-term) ----
        float sacc[16][4];
#pragma unroll
        for (int a = 0; a < 16; a++)
#pragma unroll
            for (int r = 0; r < 4; r++) sacc[a][r] = 0.f;

#pragma unroll
        for (int k16 = 0; k16 < 4; k16++) {
            uint32_t aH[4], aL[4];
            uint32_t aaddr = sQ + (uint32_t)((wr + ((lane >> 3) & 1) * 8 + (lane & 7)) * QSTR
                                             + k16 * 16 + (lane >> 4) * 8) * 2;
            ldsm4(aH, aaddr);
            ldsm4(aL, aaddr + QPL);
#pragma unroll
            for (int g = 0; g < 8; g++) {
                uint32_t baddr = sKs + (uint32_t)((g * 16 + (lane >> 4) * 8 + (lane & 7)) * QSTR
                                                  + k16 * 16 + ((lane >> 3) & 1) * 8) * 2;
                uint32_t tH[4], tL[4];
                ldsm4(tH, baddr);
                ldsm4(tL, baddr + QPL);
                mma_f16(sacc[2 * g], aH, tH);
                mma_f16(sacc[2 * g], aH, tL);
                mma_f16(sacc[2 * g], aL, tH);
                mma_f16(sacc[2 * g + 1], aH, tH + 2);
                mma_f16(sacc[2 * g + 1], aH, tL + 2);
                mma_f16(sacc[2 * g + 1], aL, tH + 2);
            }
        }

        // ---- online softmax ----
        float mx0 = -1e30f, mx1 = -1e30f;
#pragma unroll
        for (int a = 0; a < 16; a++) {
            mx0 = fmaxf(mx0, fmaxf(sacc[a][0], sacc[a][1]));
            mx1 = fmaxf(mx1, fmaxf(sacc[a][2], sacc[a][3]));
        }
        mx0 = fmaxf(mx0, __shfl_xor_sync(0xffffffffu, mx0, 1));
        mx0 = fmaxf(mx0, __shfl_xor_sync(0xffffffffu, mx0, 2));
        mx1 = fmaxf(mx1, __shfl_xor_sync(0xffffffffu, mx1, 1));
        mx1 = fmaxf(mx1, __shfl_xor_sync(0xffffffffu, mx1, 2));
        float nm0 = fmaxf(run_mx0, mx0), nm1 = fmaxf(run_mx1, mx1);
        float f0 = __expf(run_mx0 - nm0), f1 = __expf(run_mx1 - nm1);
        run_mx0 = nm0; run_mx1 = nm1;
        float s0 = 0.f, s1 = 0.f;
#pragma unroll
        for (int a = 0; a < 16; a++) {
            sacc[a][0] = __expf(sacc[a][0] - nm0); s0 += sacc[a][0];
            sacc[a][1] = __expf(sacc[a][1] - nm0); s0 += sacc[a][1];
            sacc[a][2] = __expf(sacc[a][2] - nm1); s1 += sacc[a][2];
            sacc[a][3] = __expf(sacc[a][3] - nm1); s1 += sacc[a][3];
        }
        s0 += __shfl_xor_sync(0xffffffffu, s0, 1);
        s0 += __shfl_xor_sync(0xffffffffu, s0, 2);
        s1 += __shfl_xor_sync(0xffffffffu, s1, 1);
        s1 += __shfl_xor_sync(0xffffffffu, s1, 2);
        run_s0 = run_s0 * f0 + s0;
        run_s1 = run_s1 * f1 + s1;
#pragma unroll
        for (int a = 0; a < 8; a++) {
            oacc[a][0] *= f0; oacc[a][1] *= f0;
            oacc[a][2] *= f1; oacc[a][3] *= f1;
        }

        // ---- O += P V (P hi+lo, V hi) ----
#pragma unroll
        for (int j = 0; j < 8; j++) {
            uint32_t pH[4], pL[4];
            pH[0] = pack_split_h(sacc[2 * j][0], sacc[2 * j][1], pL[0]);
            pH[1] = pack_split_h(sacc[2 * j][2], sacc[2 * j][3], pL[1]);
            pH[2] = pack_split_h(sacc[2 * j + 1][0], sacc[2 * j + 1][1], pL[2]);
            pH[3] = pack_split_h(sacc[2 * j + 1][2], sacc[2 * j + 1][3], pL[3]);
#pragma unroll
            for (int g = 0; g < 4; g++) {
                uint32_t baddr = sVs + (uint32_t)((g * 16 + (lane >> 4) * 8 + (lane & 7)) * VSTR
                                                  + j * 16 + ((lane >> 3) & 1) * 8) * 2;
                uint32_t tH[4];
                ldsm4(tH, baddr);
                mma_f16(oacc[2 * g], pH, tH);
                mma_f16(oacc[2 * g], pL, tH);
                mma_f16(oacc[2 * g + 1], pH, tH + 2);
                mma_f16(oacc[2 * g + 1], pL, tH + 2);
            }
        }
        __syncthreads();
    }

    float inv0 = 1.f / run_s0, inv1 = 1.f / run_s1;
    int r0 = wr + (lane >> 2);
    int cql = (lane & 3) * 2;
#pragma unroll
    for (int a = 0; a < 8; a++) {
        int colg = h * HDIM + a * 8 + cql;
        if (r0 < nq) {
            uint32_t lo;
            uint32_t hi = pack_split_h(oacc[a][0] * inv0, oacc[a][1] * inv0, lo);
            size_t idx = ((size_t)(be * NN + q0 + r0) * DD + colg) >> 1;
            reinterpret_cast<uint32_t*>(g_Ach)[idx] = hi;
            reinterpret_cast<uint32_t*>(g_Acl)[idx] = lo;
        }
        if (r0 + 8 < nq) {
            uint32_t lo;
            uint32_t hi = pack_split_h(oacc[a][2] * inv1, oacc[a][3] * inv1, lo);
            size_t idx = ((size_t)(be * NN + q0 + r0 + 8) * DD + colg) >> 1;
            reinterpret_cast<uint32_t*>(g_Ach)[idx] = hi;
            reinterpret_cast<uint32_t*>(g_Acl)[idx] = lo;
        }
    }
}

// ------------------------- final combine -------------------------------------
__global__ void combine_kernel(float* __restrict__ out) {
    int t = blockIdx.x * blockDim.x + threadIdx.x;
    int qid = t >> 8;
    int d4 = (t & 255) * 4;
    float w0 = g_w[qid * 2 + 0], w1 = g_w[qid * 2 + 1];
    int s0 = g_slot[qid * 2 + 0], s1 = g_slot[qid * 2 + 1];
    float4 a = *reinterpret_cast<const float4*>(g_Go + (size_t)s0 * DD + d4);
    float4 c = *reinterpret_cast<const float4*>(g_Go + (size_t)s1 * DD + d4);
    float4 o;
    o.x = w0 * a.x + w1 * c.x;
    o.y = w0 * a.y + w1 * c.y;
    o.z = w0 * a.z + w1 * c.z;
    o.w = w0 * a.w + w1 * c.w;
    *reinterpret_cast<float4*>(out + (size_t)qid * DD + d4) = o;
}

// ------------------------- launch --------------------------------------------
extern "C" void kernel_launch(void* const* d_in, const int* in_sizes, int n_in,
                              void* d_out, int out_size) {
    const float* queries = (const float*)d_in[0];
    const float* keys    = (const float*)d_in[1];
    const float* values  = (const float*)d_in[2];
    const float* Wq = (const float*)d_in[3];
    const float* bq = (const float*)d_in[4];
    const float* Wk = (const float*)d_in[5];
    const float* bk = (const float*)d_in[6];
    const float* Wv = (const float*)d_in[7];
    const float* bv = (const float*)d_in[8];
    const float* Wo = (const float*)d_in[9];
    const float* bo = (const float*)d_in[10];
    const float* Wr = (const float*)d_in[11];
    const float* br = (const float*)d_in[12];
    float* out = (float*)d_out;
    (void)in_sizes; (void)n_in; (void)out_size;

    cudaFuncSetAttribute(kvproj_mma_kernel, cudaFuncAttributeMaxDynamicSharedMemorySize, GEMM_SMEM);
    cudaFuncSetAttribute(qproj_mma_kernel, cudaFuncAttributeMaxDynamicSharedMemorySize, GEMM_SMEM);
    cudaFuncSetAttribute(oproj_mma_kernel, cudaFuncAttributeMaxDynamicSharedMemorySize, GEMM_SMEM);
    cudaFuncSetAttribute(attn_mma_kernel, cudaFuncAttributeMaxDynamicSharedMemorySize, ATTN_SMEM);

    zero_cnt_kernel<<<1, 32>>>();
    router_kernel<<<(BB * NN) / 8, 256>>>(queries, Wr, br);
    compact_kernel<<<(BB * NN * TK) / 256, 256>>>();
    conv_w_kernel<<<dim3(16, 32, 32), 256>>>(Wq, Wk, Wv, Wo);
    conv_kv_kernel<<<(2 * BB * MM * DD / 4) / 256, 256>>>(keys, values);
    gather_split_kernel<<<dim3(NN / 2, BB * EE), 256>>>(queries);
    kvproj_mma_kernel<<<dim3(8, 4, BB * EE * 2), 256, GEMM_SMEM>>>(bk, bv);
    qproj_mma_kernel<<<dim3(8, 16, BB * EE), 256, GEMM_SMEM>>>(bq);
    attn_mma_kernel<<<dim3(HH, NN / AQ, BB * EE), 256, ATTN_SMEM>>>();
    oproj_mma_kernel<<<dim3(8, 16, BB * EE), 256, GEMM_SMEM>>>(bo);
    combine_kernel<<<(BB * NN * DD / 4) / 256, 256>>>(out);
}

// round 11
// speedup vs baseline: 1.9916x; 1.3819x over previous
#include <cuda_runtime.h>
#include <cuda_fp16.h>
#include <cstdint>

#define BB 2
#define NN 2048
#define MM 4096
#define DD 1024
#define HH 16
#define EE 8
#define TK 2
#define HDIM 64
#define CHUNK 512
#define ATT_SCALE 0.125f
#define SLOTS (BB * EE * NN)

#define TKK 32
#define NKT (DD / TKK)
#define ASTR 40
#define PLANE_BYTES (128 * ASTR * 2)
#define STAGE_BYTES (2 * PLANE_BYTES)   // A, B (single plane each)
#define GEMM_SMEM   (2 * STAGE_BYTES)

// attention tiles (double-buffered K/V; V single plane)
#define AQ 128
#define QSTR 72
#define VSTR 136
#define QPL (128 * QSTR * 2)
#define VPL (64 * VSTR * 2)
#define ATTN_SMEM (6 * QPL + 2 * VPL)   // Q(2) + K(2stg x 2pl) + V(2stg x 1pl)

// ------------------------- scratch -------------------------------------------
__device__ float g_Go[(size_t)SLOTS * DD];
__device__ int   g_idx[BB * NN * TK];
__device__ float g_w[BB * NN * TK];
__device__ int   g_slot[BB * NN * TK];
__device__ int   g_qlist[BB * EE * NN];
__device__ int   g_cnt[BB * EE];
// A-operand planes (fp16, single)
__device__ __half g_Kin[(size_t)BB * MM * DD];
__device__ __half g_Vin[(size_t)BB * MM * DD];
__device__ __half g_Qc[(size_t)SLOTS * DD];
__device__ __half g_Ac[(size_t)SLOTS * DD];
// projected planes for attention
__device__ __half g_Kbh[(size_t)BB * MM * DD];   // K proj hi
__device__ __half g_Kbl[(size_t)BB * MM * DD];   // K proj lo
__device__ __half g_Vth[(size_t)BB * EE * DD * CHUNK];   // V proj transposed, hi only
__device__ __half g_Qph[(size_t)SLOTS * DD];     // Q proj hi (scaled)
__device__ __half g_Qpl[(size_t)SLOTS * DD];     // Q proj lo
// transposed weights [n][k], hi only; 0=q,1=k,2=v,3=o
__device__ __half g_Wt_h[4][(size_t)EE * DD * DD];

// ------------------------- PTX helpers ---------------------------------------
__device__ __forceinline__ uint32_t smem_u32p(const void* p) {
    return (uint32_t)__cvta_generic_to_shared(p);
}
__device__ __forceinline__ void cp_async16(uint32_t dst, const void* src) {
    asm volatile("cp.async.cg.shared.global [%0], [%1], 16;\n" :: "r"(dst), "l"(src));
}
__device__ __forceinline__ void cp_commit() {
    asm volatile("cp.async.commit_group;\n" ::: "memory");
}
__device__ __forceinline__ void cp_wait_all() {
    asm volatile("cp.async.wait_group 0;\n" ::: "memory");
}
template <int N>
__device__ __forceinline__ void cp_wait_group() {
    asm volatile("cp.async.wait_group %0;\n" :: "n"(N) : "memory");
}
__device__ __forceinline__ void ldsm4(uint32_t* r, uint32_t addr) {
    asm volatile("ldmatrix.sync.aligned.m8n8.x4.shared.b16 {%0,%1,%2,%3}, [%4];"
                 : "=r"(r[0]), "=r"(r[1]), "=r"(r[2]), "=r"(r[3]) : "r"(addr));
}
__device__ __forceinline__ void mma_f16(float* d, const uint32_t* a, const uint32_t* b) {
    asm volatile(
        "mma.sync.aligned.m16n8k16.row.col.f32.f16.f16.f32 "
        "{%0,%1,%2,%3}, {%4,%5,%6,%7}, {%8,%9}, {%0,%1,%2,%3};"
        : "+f"(d[0]), "+f"(d[1]), "+f"(d[2]), "+f"(d[3])
        : "r"(a[0]), "r"(a[1]), "r"(a[2]), "r"(a[3]), "r"(b[0]), "r"(b[1]));
}
__device__ __forceinline__ uint32_t pack_split_h(float x, float y, uint32_t& lo) {
    __half2 h2 = __floats2half2_rn(x, y);
    __half2 l2 = __floats2half2_rn(x - __half2float(__low2half(h2)),
                                   y - __half2float(__high2half(h2)));
    lo = *reinterpret_cast<uint32_t*>(&l2);
    return *reinterpret_cast<uint32_t*>(&h2);
}
__device__ __forceinline__ uint32_t pack_h(float x, float y) {
    __half2 h2 = __floats2half2_rn(x, y);
    return *reinterpret_cast<uint32_t*>(&h2);
}

// ------------------------- small kernels -------------------------------------
__global__ void zero_cnt_kernel() {
    if (threadIdx.x < BB * EE) g_cnt[threadIdx.x] = 0;
}

__global__ void router_kernel(const float* __restrict__ q,
                              const float* __restrict__ Wr,
                              const float* __restrict__ br) {
    int lane = threadIdx.x & 31;
    int qid = blockIdx.x * (blockDim.x >> 5) + (threadIdx.x >> 5);
    if (qid >= BB * NN) return;
    const float* qrow = q + (size_t)qid * DD;
    float acc[EE];
#pragma unroll
    for (int e = 0; e < EE; e++) acc[e] = 0.f;
    for (int d = lane; d < DD; d += 32) {
        float qv = qrow[d];
        const float4* w4 = reinterpret_cast<const float4*>(Wr + d * EE);
        float4 w0 = w4[0], w1 = w4[1];
        acc[0] += qv * w0.x; acc[1] += qv * w0.y;
        acc[2] += qv * w0.z; acc[3] += qv * w0.w;
        acc[4] += qv * w1.x; acc[5] += qv * w1.y;
        acc[6] += qv * w1.z; acc[7] += qv * w1.w;
    }
#pragma unroll
    for (int e = 0; e < EE; e++) {
#pragma unroll
        for (int o = 16; o > 0; o >>= 1)
            acc[e] += __shfl_xor_sync(0xffffffffu, acc[e], o);
    }
    if (lane == 0) {
        float v[EE];
#pragma unroll
        for (int e = 0; e < EE; e++) v[e] = acc[e] + br[e];
        int i0 = 0;
#pragma unroll
        for (int e = 1; e < EE; e++) if (v[e] > v[i0]) i0 = e;
        int i1 = (i0 == 0) ? 1 : 0;
#pragma unroll
        for (int e = 0; e < EE; e++) if (e != i0 && v[e] > v[i1]) i1 = e;
        float ex = __expf(v[i1] - v[i0]);
        float inv = 1.f / (1.f + ex);
        g_idx[qid * 2 + 0] = i0;
        g_idx[qid * 2 + 1] = i1;
        g_w[qid * 2 + 0] = inv;
        g_w[qid * 2 + 1] = ex * inv;
    }
}

__global__ void compact_kernel() {
    int t = blockIdx.x * blockDim.x + threadIdx.x;
    if (t >= BB * NN * TK) return;
    int qid = t >> 1;
    int b = qid / NN, n = qid % NN;
    int be = b * EE + g_idx[t];
    int pos = atomicAdd(&g_cnt[be], 1);
    g_qlist[be * NN + pos] = n;
    g_slot[t] = be * NN + pos;
}

// ------------------------- converts ------------------------------------------
__global__ void conv_w_kernel(const float* __restrict__ Wq, const float* __restrict__ Wk,
                              const float* __restrict__ Wv, const float* __restrict__ Wo) {
    __shared__ float sm[64][33];   // [k][n]
    int w = blockIdx.z >> 3, e = blockIdx.z & 7;
    const float* src = (w == 0 ? Wq : w == 1 ? Wk : w == 2 ? Wv : Wo) + (size_t)e * DD * DD;
    int k0 = blockIdx.x * 64, n0 = blockIdx.y * 32;
    int tid = threadIdx.x, rr = tid >> 5, cc = tid & 31;
#pragma unroll
    for (int i = 0; i < 8; i++)
        sm[rr + 8 * i][cc] = src[(size_t)(k0 + rr + 8 * i) * DD + n0 + cc];
    __syncthreads();
    __half* dh = g_Wt_h[w] + (size_t)e * DD * DD;
    int lane = tid & 31, wrow = tid >> 5;
#pragma unroll
    for (int j = 0; j < 4; j++) {
        int n = wrow + 8 * j;
        uint32_t h2 = pack_h(sm[lane * 2 + 0][n], sm[lane * 2 + 1][n]);
        size_t o = ((size_t)(n0 + n) * DD + k0 + lane * 2) >> 1;
        reinterpret_cast<uint32_t*>(dh)[o] = h2;
    }
}

__global__ void conv_kv_kernel(const float* __restrict__ keys,
                               const float* __restrict__ values) {
    size_t n4 = (size_t)BB * MM * DD / 4;
    size_t t = (size_t)blockIdx.x * blockDim.x + threadIdx.x;
    int which = (t >= n4);
    size_t i4 = which ? (t - n4) : t;
    float4 v = reinterpret_cast<const float4*>(which ? values : keys)[i4];
    uint32_t h[2];
    h[0] = pack_h(v.x, v.y);
    h[1] = pack_h(v.z, v.w);
    __half* dh = which ? g_Vin : g_Kin;
    reinterpret_cast<uint2*>(dh)[i4] = *reinterpret_cast<uint2*>(h);
}

__global__ void gather_split_kernel(const float* __restrict__ queries) {
    int be = blockIdx.y;
    int p = blockIdx.x * 2 + (threadIdx.x >> 7);
    if (p >= g_cnt[be]) return;
    int l128 = threadIdx.x & 127;
    int slot = be * NN + p;
    int b = be / EE;
    int n = g_qlist[be * NN + p];
    const float* src = queries + ((size_t)b * NN + n) * DD + l128 * 8;
    float4 v0 = *reinterpret_cast<const float4*>(src);
    float4 v1 = *reinterpret_cast<const float4*>(src + 4);
    uint32_t h[4];
    h[0] = pack_h(v0.x, v0.y);
    h[1] = pack_h(v0.z, v0.w);
    h[2] = pack_h(v1.x, v1.y);
    h[3] = pack_h(v1.z, v1.w);
    __half* dh = g_Qc + (size_t)slot * DD + l128 * 8;
    *reinterpret_cast<uint4*>(dh) = *reinterpret_cast<const uint4*>(h);
}

// ------------------------- HMMA fp16 GEMM core --------------------------------
// C = A * B^T, single fp16 plane each: 1 MMA per atom.
// MODE 0: fp32 out. 1: fp16 hi+lo planes [row][DD]. 2: V-transposed hi only.
// 3: fp16 hi+lo planes [row][DD] scaled by ATT_SCALE.
template <int MODE>
__device__ __forceinline__ void gemm_body(
    const __half* __restrict__ Ah, int rowA0,
    const __half* __restrict__ Bh, int rowB0,
    int climit, const float* __restrict__ bias, int n0,
    float* __restrict__ C, __half* __restrict__ Ph, __half* __restrict__ Pl,
    long crow0, size_t vtb)
{
    extern __shared__ __align__(128) char smx[];
    int tid = threadIdx.x, lane = tid & 31, warp = tid >> 5;
    uint32_t sm0 = smem_u32p(smx);

    int row0 = tid >> 2, col0 = (tid & 3) * 8;
    const __half* gsrc[2];
    gsrc[0] = Ah + (size_t)(rowA0 + row0) * DD + col0;
    gsrc[1] = Bh + (size_t)(rowB0 + row0) * DD + col0;
    uint32_t soff0 = (uint32_t)(row0 * ASTR + col0) * 2;
    uint32_t soff1 = soff0 + 64 * ASTR * 2;

    int wr = (warp >> 2) * 64, wc = (warp & 3) * 32;
    uint32_t aRow = (uint32_t)(wr + ((lane >> 3) & 1) * 8 + (lane & 7));
    uint32_t aCol = (uint32_t)((lane >> 4) * 8);
    uint32_t bRow = (uint32_t)(wc + (lane >> 4) * 8 + (lane & 7));
    uint32_t bCol = (uint32_t)(((lane >> 3) & 1) * 8);

    float acc[4][4][4];
#pragma unroll
    for (int i = 0; i < 4; i++)
#pragma unroll
        for (int j = 0; j < 4; j++)
#pragma unroll
            for (int r = 0; r < 4; r++) acc[i][j][r] = 0.f;

    {
        uint32_t base = sm0;
#pragma unroll
        for (int p = 0; p < 2; p++) {
            cp_async16(base + p * PLANE_BYTES + soff0, gsrc[p]);
            cp_async16(base + p * PLANE_BYTES + soff1, gsrc[p] + (size_t)64 * DD);
        }
        cp_commit();
    }

    for (int kt = 0; kt < NKT; kt++) {
        int st = kt & 1;
        cp_wait_all();
        __syncthreads();
        if (kt + 1 < NKT) {
            uint32_t base = sm0 + (st ^ 1) * STAGE_BYTES;
            int k0 = (kt + 1) * TKK;
#pragma unroll
            for (int p = 0; p < 2; p++) {
                cp_async16(base + p * PLANE_BYTES + soff0, gsrc[p] + k0);
                cp_async16(base + p * PLANE_BYTES + soff1, gsrc[p] + (size_t)64 * DD + k0);
            }
            cp_commit();
        }
        uint32_t base = sm0 + st * STAGE_BYTES;
#pragma unroll
        for (int k16 = 0; k16 < 2; k16++) {
            uint32_t ah[4][4], bh[4][2];
#pragma unroll
            for (int ma = 0; ma < 4; ma++) {
                uint32_t addr = base + ((aRow + ma * 16) * ASTR + k16 * 16 + aCol) * 2;
                ldsm4(ah[ma], addr);
            }
#pragma unroll
            for (int g = 0; g < 2; g++) {
                uint32_t addr = base + PLANE_BYTES
                              + ((bRow + g * 16) * ASTR + k16 * 16 + bCol) * 2;
                uint32_t t4[4];
                ldsm4(t4, addr);
                bh[2 * g][0] = t4[0]; bh[2 * g][1] = t4[1];
                bh[2 * g + 1][0] = t4[2]; bh[2 * g + 1][1] = t4[3];
            }
#pragma unroll
            for (int ma = 0; ma < 4; ma++)
#pragma unroll
                for (int na = 0; na < 4; na++)
                    mma_f16(acc[ma][na], ah[ma], bh[na]);
        }
    }

    int rql = lane >> 2, cql = (lane & 3) * 2;
#pragma unroll
    for (int na = 0; na < 4; na++) {
        int colg = n0 + wc + na * 8 + cql;
        float b0 = bias[colg], b1 = bias[colg + 1];
#pragma unroll
        for (int ma = 0; ma < 4; ma++) {
#pragma unroll
            for (int hh = 0; hh < 2; hh++) {
                int rowt = wr + ma * 16 + rql + hh * 8;
                if (rowt >= climit) continue;
                float v0 = acc[ma][na][hh * 2 + 0] + b0;
                float v1 = acc[ma][na][hh * 2 + 1] + b1;
                if (MODE == 0) {
                    *reinterpret_cast<float2*>(C + (size_t)(crow0 + rowt) * DD + colg) =
                        make_float2(v0, v1);
                } else if (MODE == 1 || MODE == 3) {
                    if (MODE == 3) { v0 *= ATT_SCALE; v1 *= ATT_SCALE; }
                    uint32_t lo;
                    uint32_t hi = pack_split_h(v0, v1, lo);
                    size_t idx = ((size_t)(crow0 + rowt) * DD + colg) >> 1;
                    reinterpret_cast<uint32_t*>(Ph)[idx] = hi;
                    reinterpret_cast<uint32_t*>(Pl)[idx] = lo;
                } else {  // MODE 2: transposed V, hi only
                    size_t key = (size_t)(crow0 + rowt);
                    Ph[vtb + (size_t)colg * CHUNK + key] = __float2half_rn(v0);
                    Ph[vtb + (size_t)(colg + 1) * CHUNK + key] = __float2half_rn(v1);
                }
            }
        }
    }
}

__global__ __launch_bounds__(256) void kvproj_mma_kernel(
    const float* __restrict__ bk, const float* __restrict__ bv) {
    int z = blockIdx.z;
    int which = z & 1, be = z >> 1;
    int b = be / EE, e = be % EE;
    int rowA0 = b * MM + e * CHUNK + blockIdx.y * 128;
    if (which == 0) {
        gemm_body<1>(g_Kin, rowA0,
                     g_Wt_h[1], e * DD + blockIdx.x * 128,
                     128, bk + e * DD, blockIdx.x * 128,
                     nullptr, g_Kbh, g_Kbl, rowA0, 0);
    } else {
        gemm_body<2>(g_Vin, rowA0,
                     g_Wt_h[2], e * DD + blockIdx.x * 128,
                     128, bv + e * DD, blockIdx.x * 128,
                     nullptr, g_Vth, nullptr, blockIdx.y * 128, (size_t)be * DD * CHUNK);
    }
}

__global__ __launch_bounds__(256) void qproj_mma_kernel(const float* __restrict__ bq) {
    int be = blockIdx.z;
    int cnt = g_cnt[be];
    int m0 = blockIdx.y * 128;
    if (m0 >= cnt) return;
    int e = be % EE;
    gemm_body<3>(g_Qc, be * NN + m0,
                 g_Wt_h[0], e * DD + blockIdx.x * 128,
                 cnt - m0, bq + e * DD, blockIdx.x * 128,
                 nullptr, g_Qph, g_Qpl, be * NN + m0, 0);
}

__global__ __launch_bounds__(256) void oproj_mma_kernel(const float* __restrict__ bo) {
    int be = blockIdx.z;
    int cnt = g_cnt[be];
    int m0 = blockIdx.y * 128;
    if (m0 >= cnt) return;
    int e = be % EE;
    gemm_body<0>(g_Ac, be * NN + m0,
                 g_Wt_h[3], e * DD + blockIdx.x * 128,
                 cnt - m0, bo + e * DD, blockIdx.x * 128,
                 g_Go, nullptr, nullptr, be * NN + m0, 0);
}

// ------------------------- HMMA flash attention -------------------------------
// QK: 3-term (Q hi+lo x K hi+lo, drop lo*lo). PV: P hi x V hi (1-term).
__global__ __launch_bounds__(256, 1) void attn_mma_kernel() {
    extern __shared__ __align__(128) char smb[];
    int h = blockIdx.x, qt = blockIdx.y, be = blockIdx.z;
    int cnt = g_cnt[be];
    int q0 = qt * AQ;
    if (q0 >= cnt) return;
    int nq = min(AQ, cnt - q0);
    int b = be / EE, e = be % EE;
    int tid = threadIdx.x, lane = tid & 31, warp = tid >> 5;
    int wr = warp * 16;

    uint32_t sQ = smem_u32p(smb);
    uint32_t sK0 = sQ + 2 * QPL;
    uint32_t sV0 = sK0 + 4 * QPL;

    size_t kbase = (size_t)(b * MM + e * CHUNK) * DD + h * HDIM;
    size_t vbase = ((size_t)be * DD + h * HDIM) * CHUNK;

    auto load_kv = [&](int ktile, int stg) {
        uint32_t sKs = sK0 + stg * 2 * QPL;
        uint32_t sVs = sV0 + stg * VPL;
#pragma unroll
        for (int i = 0; i < 4; i++) {
            int cid = tid + 256 * i;
            int krow = cid >> 3, kc = (cid & 7) * 8;
            uint32_t kd = (uint32_t)(krow * QSTR + kc) * 2;
            size_t ks = kbase + (size_t)(ktile * 128 + krow) * DD + kc;
            cp_async16(sKs + kd, g_Kbh + ks);
            cp_async16(sKs + QPL + kd, g_Kbl + ks);
            // V hi plane: 64 d-rows x 16 chunks = 1024 chunks
            int vrow = cid >> 4, vc = (cid & 15) * 8;
            uint32_t vd = (uint32_t)(vrow * VSTR + vc) * 2;
            size_t vs = vbase + (size_t)vrow * CHUNK + ktile * 128 + vc;
            cp_async16(sVs + vd, g_Vth + vs);
        }
    };

#pragma unroll
    for (int i = 0; i < 4; i++) {
        int cid = tid + 256 * i;
        int row = cid >> 3, c8 = (cid & 7) * 8;
        int gr = be * NN + q0 + min(row, nq - 1);
        uint32_t d = (uint32_t)(row * QSTR + c8) * 2;
        cp_async16(sQ + d, g_Qph + (size_t)gr * DD + h * HDIM + c8);
        cp_async16(sQ + QPL + d, g_Qpl + (size_t)gr * DD + h * HDIM + c8);
    }
    load_kv(0, 0);
    cp_commit();

    float oacc[8][4];
#pragma unroll
    for (int a = 0; a < 8; a++)
#pragma unroll
        for (int r = 0; r < 4; r++) oacc[a][r] = 0.f;
    float run_mx0 = -1e30f, run_mx1 = -1e30f, run_s0 = 0.f, run_s1 = 0.f;

    for (int kt = 0; kt < CHUNK / 128; kt++) {
        int stg = kt & 1;
        if (kt + 1 < CHUNK / 128) {
            load_kv(kt + 1, stg ^ 1);
            cp_commit();
            cp_wait_group<1>();
        } else {
            cp_wait_group<0>();
        }
        __syncthreads();
        uint32_t sKs = sK0 + stg * 2 * QPL;
        uint32_t sVs = sV0 + stg * VPL;

        // ---- S = Q K^T (3-term) ----
        float sacc[16][4];
#pragma unroll
        for (int a = 0; a < 16; a++)
#pragma unroll
            for (int r = 0; r < 4; r++) sacc[a][r] = 0.f;

#pragma unroll
        for (int k16 = 0; k16 < 4; k16++) {
            uint32_t aH[4], aL[4];
            uint32_t aaddr = sQ + (uint32_t)((wr + ((lane >> 3) & 1) * 8 + (lane & 7)) * QSTR
                                             + k16 * 16 + (lane >> 4) * 8) * 2;
            ldsm4(aH, aaddr);
            ldsm4(aL, aaddr + QPL);
#pragma unroll
            for (int g = 0; g < 8; g++) {
                uint32_t baddr = sKs + (uint32_t)((g * 16 + (lane >> 4) * 8 + (lane & 7)) * QSTR
                                                  + k16 * 16 + ((lane >> 3) & 1) * 8) * 2;
                uint32_t tH[4], tL[4];
                ldsm4(tH, baddr);
                ldsm4(tL, baddr + QPL);
                mma_f16(sacc[2 * g], aH, tH);
                mma_f16(sacc[2 * g], aH, tL);
                mma_f16(sacc[2 * g], aL, tH);
                mma_f16(sacc[2 * g + 1], aH, tH + 2);
                mma_f16(sacc[2 * g + 1], aH, tL + 2);
                mma_f16(sacc[2 * g + 1], aL, tH + 2);
            }
        }

        // ---- online softmax ----
        float mx0 = -1e30f, mx1 = -1e30f;
#pragma unroll
        for (int a = 0; a < 16; a++) {
            mx0 = fmaxf(mx0, fmaxf(sacc[a][0], sacc[a][1]));
            mx1 = fmaxf(mx1, fmaxf(sacc[a][2], sacc[a][3]));
        }
        mx0 = fmaxf(mx0, __shfl_xor_sync(0xffffffffu, mx0, 1));
        mx0 = fmaxf(mx0, __shfl_xor_sync(0xffffffffu, mx0, 2));
        mx1 = fmaxf(mx1, __shfl_xor_sync(0xffffffffu, mx1, 1));
        mx1 = fmaxf(mx1, __shfl_xor_sync(0xffffffffu, mx1, 2));
        float nm0 = fmaxf(run_mx0, mx0), nm1 = fmaxf(run_mx1, mx1);
        float f0 = __expf(run_mx0 - nm0), f1 = __expf(run_mx1 - nm1);
        run_mx0 = nm0; run_mx1 = nm1;
        float s0 = 0.f, s1 = 0.f;
#pragma unroll
        for (int a = 0; a < 16; a++) {
            sacc[a][0] = __expf(sacc[a][0] - nm0); s0 += sacc[a][0];
            sacc[a][1] = __expf(sacc[a][1] - nm0); s0 += sacc[a][1];
            sacc[a][2] = __expf(sacc[a][2] - nm1); s1 += sacc[a][2];
            sacc[a][3] = __expf(sacc[a][3] - nm1); s1 += sacc[a][3];
        }
        s0 += __shfl_xor_sync(0xffffffffu, s0, 1);
        s0 += __shfl_xor_sync(0xffffffffu, s0, 2);
        s1 += __shfl_xor_sync(0xffffffffu, s1, 1);
        s1 += __shfl_xor_sync(0xffffffffu, s1, 2);
        run_s0 = run_s0 * f0 + s0;
        run_s1 = run_s1 * f1 + s1;
#pragma unroll
        for (int a = 0; a < 8; a++) {
            oacc[a][0] *= f0; oacc[a][1] *= f0;
            oacc[a][2] *= f1; oacc[a][3] *= f1;
        }

        // ---- O += P V (P hi, V hi) ----
#pragma unroll
        for (int j = 0; j < 8; j++) {
            uint32_t pH[4];
            pH[0] = pack_h(sacc[2 * j][0], sacc[2 * j][1]);
            pH[1] = pack_h(sacc[2 * j][2], sacc[2 * j][3]);
            pH[2] = pack_h(sacc[2 * j + 1][0], sacc[2 * j + 1][1]);
            pH[3] = pack_h(sacc[2 * j + 1][2], sacc[2 * j + 1][3]);
#pragma unroll
            for (int g = 0; g < 4; g++) {
                uint32_t baddr = sVs + (uint32_t)((g * 16 + (lane >> 4) * 8 + (lane & 7)) * VSTR
                                                  + j * 16 + ((lane >> 3) & 1) * 8) * 2;
                uint32_t tH[4];
                ldsm4(tH, baddr);
                mma_f16(oacc[2 * g], pH, tH);
                mma_f16(oacc[2 * g + 1], pH, tH + 2);
            }
        }
        __syncthreads();
    }

    float inv0 = 1.f / run_s0, inv1 = 1.f / run_s1;
    int r0 = wr + (lane >> 2);
    int cql = (lane & 3) * 2;
#pragma unroll
    for (int a = 0; a < 8; a++) {
        int colg = h * HDIM + a * 8 + cql;
        if (r0 < nq) {
            uint32_t hi = pack_h(oacc[a][0] * inv0, oacc[a][1] * inv0);
            size_t idx = ((size_t)(be * NN + q0 + r0) * DD + colg) >> 1;
            reinterpret_cast<uint32_t*>(g_Ac)[idx] = hi;
        }
        if (r0 + 8 < nq) {
            uint32_t hi = pack_h(oacc[a][2] * inv1, oacc[a][3] * inv1);
            size_t idx = ((size_t)(be * NN + q0 + r0 + 8) * DD + colg) >> 1;
            reinterpret_cast<uint32_t*>(g_Ac)[idx] = hi;
        }
    }
}

// ------------------------- final combine -------------------------------------
__global__ void combine_kernel(float* __restrict__ out) {
    int t = blockIdx.x * blockDim.x + threadIdx.x;
    int qid = t >> 8;
    int d4 = (t & 255) * 4;
    float w0 = g_w[qid * 2 + 0], w1 = g_w[qid * 2 + 1];
    int s0 = g_slot[qid * 2 + 0], s1 = g_slot[qid * 2 + 1];
    float4 a = *reinterpret_cast<const float4*>(g_Go + (size_t)s0 * DD + d4);
    float4 c = *reinterpret_cast<const float4*>(g_Go + (size_t)s1 * DD + d4);
    float4 o;
    o.x = w0 * a.x + w1 * c.x;
    o.y = w0 * a.y + w1 * c.y;
    o.z = w0 * a.z + w1 * c.z;
    o.w = w0 * a.w + w1 * c.w;
    *reinterpret_cast<float4*>(out + (size_t)qid * DD + d4) = o;
}

// ------------------------- launch --------------------------------------------
extern "C" void kernel_launch(void* const* d_in, const int* in_sizes, int n_in,
                              void* d_out, int out_size) {
    const float* queries = (const float*)d_in[0];
    const float* keys    = (const float*)d_in[1];
    const float* values  = (const float*)d_in[2];
    const float* Wq = (const float*)d_in[3];
    const float* bq = (const float*)d_in[4];
    const float* Wk = (const float*)d_in[5];
    const float* bk = (const float*)d_in[6];
    const float* Wv = (const float*)d_in[7];
    const float* bv = (const float*)d_in[8];
    const float* Wo = (const float*)d_in[9];
    const float* bo = (const float*)d_in[10];
    const float* Wr = (const float*)d_in[11];
    const float* br = (const float*)d_in[12];
    float* out = (float*)d_out;
    (void)in_sizes; (void)n_in; (void)out_size;

    cudaFuncSetAttribute(kvproj_mma_kernel, cudaFuncAttributeMaxDynamicSharedMemorySize, GEMM_SMEM);
    cudaFuncSetAttribute(qproj_mma_kernel, cudaFuncAttributeMaxDynamicSharedMemorySize, GEMM_SMEM);
    cudaFuncSetAttribute(oproj_mma_kernel, cudaFuncAttributeMaxDynamicSharedMemorySize, GEMM_SMEM);
    cudaFuncSetAttribute(attn_mma_kernel, cudaFuncAttributeMaxDynamicSharedMemorySize, ATTN_SMEM);

    zero_cnt_kernel<<<1, 32>>>();
    router_kernel<<<(BB * NN) / 8, 256>>>(queries, Wr, br);
    compact_kernel<<<(BB * NN * TK) / 256, 256>>>();
    conv_w_kernel<<<dim3(16, 32, 32), 256>>>(Wq, Wk, Wv, Wo);
    conv_kv_kernel<<<(2 * BB * MM * DD / 4) / 256, 256>>>(keys, values);
    gather_split_kernel<<<dim3(NN / 2, BB * EE), 256>>>(queries);
    kvproj_mma_kernel<<<dim3(8, 4, BB * EE * 2), 256, GEMM_SMEM>>>(bk, bv);
    qproj_mma_kernel<<<dim3(8, 16, BB * EE), 256, GEMM_SMEM>>>(bq);
    attn_mma_kernel<<<dim3(HH, NN / AQ, BB * EE), 256, ATTN_SMEM>>>();
    oproj_mma_kernel<<<dim3(8, 16, BB * EE), 256, GEMM_SMEM>>>(bo);
    combine_kernel<<<(BB * NN * DD / 4) / 256, 256>>>(out);
}

// round 12
// speedup vs baseline: 2.0920x; 1.0504x over previous
#include <cuda_runtime.h>
#include <cuda_fp16.h>
#include <cstdint>

#define BB 2
#define NN 2048
#define MM 4096
#define DD 1024
#define HH 16
#define EE 8
#define TK 2
#define HDIM 64
#define CHUNK 512
#define ATT_SCALE 0.125f
#define SLOTS (BB * EE * NN)

#define TKK 32
#define NKT (DD / TKK)
#define ASTR 40
#define PLANE_BYTES (128 * ASTR * 2)
#define STAGE_BYTES (2 * PLANE_BYTES)   // A, B (single plane each)
#define GEMM_SMEM   (2 * STAGE_BYTES)

// attention tiles (double-buffered K/V; K and V single plane, Q hi+lo)
#define AQ 128
#define QSTR 72
#define VSTR 136
#define QPL (128 * QSTR * 2)
#define VPL (64 * VSTR * 2)
#define ATTN_SMEM (4 * QPL + 2 * VPL)   // Q(2pl) + K(2stg x 1pl) + V(2stg x 1pl)

// ------------------------- scratch -------------------------------------------
__device__ float g_Go[(size_t)SLOTS * DD];
__device__ float g_w[BB * NN * TK];
__device__ int   g_slot[BB * NN * TK];
__device__ int   g_qlist[BB * EE * NN];
__device__ int   g_cnt[BB * EE];
// A-operand planes (fp16, single)
__device__ __half g_Kin[(size_t)BB * MM * DD];
__device__ __half g_Vin[(size_t)BB * MM * DD];
__device__ __half g_Qc[(size_t)SLOTS * DD];
__device__ __half g_Ac[(size_t)SLOTS * DD];
// projected planes for attention
__device__ __half g_Kb[(size_t)BB * MM * DD];    // K proj (fp16, single plane)
__device__ __half g_Vth[(size_t)BB * EE * DD * CHUNK];   // V proj transposed
__device__ __half g_Qph[(size_t)SLOTS * DD];     // Q proj hi (scaled)
__device__ __half g_Qpl[(size_t)SLOTS * DD];     // Q proj lo
// transposed weights [n][k]; 0=q,1=k,2=v,3=o
__device__ __half g_Wt_h[4][(size_t)EE * DD * DD];

// ------------------------- PTX helpers ---------------------------------------
__device__ __forceinline__ uint32_t smem_u32p(const void* p) {
    return (uint32_t)__cvta_generic_to_shared(p);
}
__device__ __forceinline__ void cp_async16(uint32_t dst, const void* src) {
    asm volatile("cp.async.cg.shared.global [%0], [%1], 16;\n" :: "r"(dst), "l"(src));
}
__device__ __forceinline__ void cp_commit() {
    asm volatile("cp.async.commit_group;\n" ::: "memory");
}
__device__ __forceinline__ void cp_wait_all() {
    asm volatile("cp.async.wait_group 0;\n" ::: "memory");
}
template <int N>
__device__ __forceinline__ void cp_wait_group() {
    asm volatile("cp.async.wait_group %0;\n" :: "n"(N) : "memory");
}
__device__ __forceinline__ void ldsm4(uint32_t* r, uint32_t addr) {
    asm volatile("ldmatrix.sync.aligned.m8n8.x4.shared.b16 {%0,%1,%2,%3}, [%4];"
                 : "=r"(r[0]), "=r"(r[1]), "=r"(r[2]), "=r"(r[3]) : "r"(addr));
}
__device__ __forceinline__ void mma_f16(float* d, const uint32_t* a, const uint32_t* b) {
    asm volatile(
        "mma.sync.aligned.m16n8k16.row.col.f32.f16.f16.f32 "
        "{%0,%1,%2,%3}, {%4,%5,%6,%7}, {%8,%9}, {%0,%1,%2,%3};"
        : "+f"(d[0]), "+f"(d[1]), "+f"(d[2]), "+f"(d[3])
        : "r"(a[0]), "r"(a[1]), "r"(a[2]), "r"(a[3]), "r"(b[0]), "r"(b[1]));
}
__device__ __forceinline__ uint32_t pack_split_h(float x, float y, uint32_t& lo) {
    __half2 h2 = __floats2half2_rn(x, y);
    __half2 l2 = __floats2half2_rn(x - __half2float(__low2half(h2)),
                                   y - __half2float(__high2half(h2)));
    lo = *reinterpret_cast<uint32_t*>(&l2);
    return *reinterpret_cast<uint32_t*>(&h2);
}
__device__ __forceinline__ uint32_t pack_h(float x, float y) {
    __half2 h2 = __floats2half2_rn(x, y);
    return *reinterpret_cast<uint32_t*>(&h2);
}

// ------------------------- small kernels -------------------------------------
__global__ void zero_cnt_kernel() {
    if (threadIdx.x < BB * EE) g_cnt[threadIdx.x] = 0;
}

// router + fused compaction
__global__ void router_kernel(const float* __restrict__ q,
                              const float* __restrict__ Wr,
                              const float* __restrict__ br) {
    int lane = threadIdx.x & 31;
    int qid = blockIdx.x * (blockDim.x >> 5) + (threadIdx.x >> 5);
    if (qid >= BB * NN) return;
    const float* qrow = q + (size_t)qid * DD;
    float acc[EE];
#pragma unroll
    for (int e = 0; e < EE; e++) acc[e] = 0.f;
    for (int d = lane; d < DD; d += 32) {
        float qv = qrow[d];
        const float4* w4 = reinterpret_cast<const float4*>(Wr + d * EE);
        float4 w0 = w4[0], w1 = w4[1];
        acc[0] += qv * w0.x; acc[1] += qv * w0.y;
        acc[2] += qv * w0.z; acc[3] += qv * w0.w;
        acc[4] += qv * w1.x; acc[5] += qv * w1.y;
        acc[6] += qv * w1.z; acc[7] += qv * w1.w;
    }
#pragma unroll
    for (int e = 0; e < EE; e++) {
#pragma unroll
        for (int o = 16; o > 0; o >>= 1)
            acc[e] += __shfl_xor_sync(0xffffffffu, acc[e], o);
    }
    if (lane == 0) {
        float v[EE];
#pragma unroll
        for (int e = 0; e < EE; e++) v[e] = acc[e] + br[e];
        int i0 = 0;
#pragma unroll
        for (int e = 1; e < EE; e++) if (v[e] > v[i0]) i0 = e;
        int i1 = (i0 == 0) ? 1 : 0;
#pragma unroll
        for (int e = 0; e < EE; e++) if (e != i0 && v[e] > v[i1]) i1 = e;
        float ex = __expf(v[i1] - v[i0]);
        float inv = 1.f / (1.f + ex);
        g_w[qid * 2 + 0] = inv;
        g_w[qid * 2 + 1] = ex * inv;
        int b = qid / NN, n = qid % NN;
        int be0 = b * EE + i0;
        int p0 = atomicAdd(&g_cnt[be0], 1);
        g_qlist[be0 * NN + p0] = n;
        g_slot[qid * 2 + 0] = be0 * NN + p0;
        int be1 = b * EE + i1;
        int p1 = atomicAdd(&g_cnt[be1], 1);
        g_qlist[be1 * NN + p1] = n;
        g_slot[qid * 2 + 1] = be1 * NN + p1;
    }
}

// ------------------------- converts ------------------------------------------
__global__ void conv_w_kernel(const float* __restrict__ Wq, const float* __restrict__ Wk,
                              const float* __restrict__ Wv, const float* __restrict__ Wo) {
    __shared__ float sm[64][33];   // [k][n]
    int w = blockIdx.z >> 3, e = blockIdx.z & 7;
    const float* src = (w == 0 ? Wq : w == 1 ? Wk : w == 2 ? Wv : Wo) + (size_t)e * DD * DD;
    int k0 = blockIdx.x * 64, n0 = blockIdx.y * 32;
    int tid = threadIdx.x, rr = tid >> 5, cc = tid & 31;
#pragma unroll
    for (int i = 0; i < 8; i++)
        sm[rr + 8 * i][cc] = src[(size_t)(k0 + rr + 8 * i) * DD + n0 + cc];
    __syncthreads();
    __half* dh = g_Wt_h[w] + (size_t)e * DD * DD;
    int lane = tid & 31, wrow = tid >> 5;
#pragma unroll
    for (int j = 0; j < 4; j++) {
        int n = wrow + 8 * j;
        uint32_t h2 = pack_h(sm[lane * 2 + 0][n], sm[lane * 2 + 1][n]);
        size_t o = ((size_t)(n0 + n) * DD + k0 + lane * 2) >> 1;
        reinterpret_cast<uint32_t*>(dh)[o] = h2;
    }
}

__global__ void conv_kv_kernel(const float* __restrict__ keys,
                               const float* __restrict__ values) {
    size_t n4 = (size_t)BB * MM * DD / 4;
    size_t t = (size_t)blockIdx.x * blockDim.x + threadIdx.x;
    int which = (t >= n4);
    size_t i4 = which ? (t - n4) : t;
    float4 v = reinterpret_cast<const float4*>(which ? values : keys)[i4];
    uint32_t h[2];
    h[0] = pack_h(v.x, v.y);
    h[1] = pack_h(v.z, v.w);
    __half* dh = which ? g_Vin : g_Kin;
    reinterpret_cast<uint2*>(dh)[i4] = *reinterpret_cast<uint2*>(h);
}

__global__ void gather_split_kernel(const float* __restrict__ queries) {
    int be = blockIdx.y;
    int p = blockIdx.x * 2 + (threadIdx.x >> 7);
    if (p >= g_cnt[be]) return;
    int l128 = threadIdx.x & 127;
    int slot = be * NN + p;
    int b = be / EE;
    int n = g_qlist[be * NN + p];
    const float* src = queries + ((size_t)b * NN + n) * DD + l128 * 8;
    float4 v0 = *reinterpret_cast<const float4*>(src);
    float4 v1 = *reinterpret_cast<const float4*>(src + 4);
    uint32_t h[4];
    h[0] = pack_h(v0.x, v0.y);
    h[1] = pack_h(v0.z, v0.w);
    h[2] = pack_h(v1.x, v1.y);
    h[3] = pack_h(v1.z, v1.w);
    __half* dh = g_Qc + (size_t)slot * DD + l128 * 8;
    *reinterpret_cast<uint4*>(dh) = *reinterpret_cast<const uint4*>(h);
}

// ------------------------- HMMA fp16 GEMM core --------------------------------
// C = A * B^T, single fp16 plane each: 1 MMA per atom.
// MODE 0: fp32 out. 1: fp16 single plane [row][DD]. 2: V-transposed single.
// 3: fp16 hi+lo planes [row][DD] scaled by ATT_SCALE.
template <int MODE>
__device__ __forceinline__ void gemm_body(
    const __half* __restrict__ Ah, int rowA0,
    const __half* __restrict__ Bh, int rowB0,
    int climit, const float* __restrict__ bias, int n0,
    float* __restrict__ C, __half* __restrict__ Ph, __half* __restrict__ Pl,
    long crow0, size_t vtb)
{
    extern __shared__ __align__(128) char smx[];
    int tid = threadIdx.x, lane = tid & 31, warp = tid >> 5;
    uint32_t sm0 = smem_u32p(smx);

    int row0 = tid >> 2, col0 = (tid & 3) * 8;
    const __half* gsrc[2];
    gsrc[0] = Ah + (size_t)(rowA0 + row0) * DD + col0;
    gsrc[1] = Bh + (size_t)(rowB0 + row0) * DD + col0;
    uint32_t soff0 = (uint32_t)(row0 * ASTR + col0) * 2;
    uint32_t soff1 = soff0 + 64 * ASTR * 2;

    int wr = (warp >> 2) * 64, wc = (warp & 3) * 32;
    uint32_t aRow = (uint32_t)(wr + ((lane >> 3) & 1) * 8 + (lane & 7));
    uint32_t aCol = (uint32_t)((lane >> 4) * 8);
    uint32_t bRow = (uint32_t)(wc + (lane >> 4) * 8 + (lane & 7));
    uint32_t bCol = (uint32_t)(((lane >> 3) & 1) * 8);

    float acc[4][4][4];
#pragma unroll
    for (int i = 0; i < 4; i++)
#pragma unroll
        for (int j = 0; j < 4; j++)
#pragma unroll
            for (int r = 0; r < 4; r++) acc[i][j][r] = 0.f;

    {
        uint32_t base = sm0;
#pragma unroll
        for (int p = 0; p < 2; p++) {
            cp_async16(base + p * PLANE_BYTES + soff0, gsrc[p]);
            cp_async16(base + p * PLANE_BYTES + soff1, gsrc[p] + (size_t)64 * DD);
        }
        cp_commit();
    }

    for (int kt = 0; kt < NKT; kt++) {
        int st = kt & 1;
        cp_wait_all();
        __syncthreads();
        if (kt + 1 < NKT) {
            uint32_t base = sm0 + (st ^ 1) * STAGE_BYTES;
            int k0 = (kt + 1) * TKK;
#pragma unroll
            for (int p = 0; p < 2; p++) {
                cp_async16(base + p * PLANE_BYTES + soff0, gsrc[p] + k0);
                cp_async16(base + p * PLANE_BYTES + soff1, gsrc[p] + (size_t)64 * DD + k0);
            }
            cp_commit();
        }
        uint32_t base = sm0 + st * STAGE_BYTES;
#pragma unroll
        for (int k16 = 0; k16 < 2; k16++) {
            uint32_t ah[4][4], bh[4][2];
#pragma unroll
            for (int ma = 0; ma < 4; ma++) {
                uint32_t addr = base + ((aRow + ma * 16) * ASTR + k16 * 16 + aCol) * 2;
                ldsm4(ah[ma], addr);
            }
#pragma unroll
            for (int g = 0; g < 2; g++) {
                uint32_t addr = base + PLANE_BYTES
                              + ((bRow + g * 16) * ASTR + k16 * 16 + bCol) * 2;
                uint32_t t4[4];
                ldsm4(t4, addr);
                bh[2 * g][0] = t4[0]; bh[2 * g][1] = t4[1];
                bh[2 * g + 1][0] = t4[2]; bh[2 * g + 1][1] = t4[3];
            }
#pragma unroll
            for (int ma = 0; ma < 4; ma++)
#pragma unroll
                for (int na = 0; na < 4; na++)
                    mma_f16(acc[ma][na], ah[ma], bh[na]);
        }
    }

    int rql = lane >> 2, cql = (lane & 3) * 2;
#pragma unroll
    for (int na = 0; na < 4; na++) {
        int colg = n0 + wc + na * 8 + cql;
        float b0 = bias[colg], b1 = bias[colg + 1];
#pragma unroll
        for (int ma = 0; ma < 4; ma++) {
#pragma unroll
            for (int hh = 0; hh < 2; hh++) {
                int rowt = wr + ma * 16 + rql + hh * 8;
                if (rowt >= climit) continue;
                float v0 = acc[ma][na][hh * 2 + 0] + b0;
                float v1 = acc[ma][na][hh * 2 + 1] + b1;
                if (MODE == 0) {
                    *reinterpret_cast<float2*>(C + (size_t)(crow0 + rowt) * DD + colg) =
                        make_float2(v0, v1);
                } else if (MODE == 1) {
                    size_t idx = ((size_t)(crow0 + rowt) * DD + colg) >> 1;
                    reinterpret_cast<uint32_t*>(Ph)[idx] = pack_h(v0, v1);
                } else if (MODE == 3) {
                    v0 *= ATT_SCALE; v1 *= ATT_SCALE;
                    uint32_t lo;
                    uint32_t hi = pack_split_h(v0, v1, lo);
                    size_t idx = ((size_t)(crow0 + rowt) * DD + colg) >> 1;
                    reinterpret_cast<uint32_t*>(Ph)[idx] = hi;
                    reinterpret_cast<uint32_t*>(Pl)[idx] = lo;
                } else {  // MODE 2: transposed V
                    size_t key = (size_t)(crow0 + rowt);
                    Ph[vtb + (size_t)colg * CHUNK + key] = __float2half_rn(v0);
                    Ph[vtb + (size_t)(colg + 1) * CHUNK + key] = __float2half_rn(v1);
                }
            }
        }
    }
}

__global__ __launch_bounds__(256) void kvproj_mma_kernel(
    const float* __restrict__ bk, const float* __restrict__ bv) {
    int z = blockIdx.z;
    int which = z & 1, be = z >> 1;
    int b = be / EE, e = be % EE;
    int rowA0 = b * MM + e * CHUNK + blockIdx.y * 128;
    if (which == 0) {
        gemm_body<1>(g_Kin, rowA0,
                     g_Wt_h[1], e * DD + blockIdx.x * 128,
                     128, bk + e * DD, blockIdx.x * 128,
                     nullptr, g_Kb, nullptr, rowA0, 0);
    } else {
        gemm_body<2>(g_Vin, rowA0,
                     g_Wt_h[2], e * DD + blockIdx.x * 128,
                     128, bv + e * DD, blockIdx.x * 128,
                     nullptr, g_Vth, nullptr, blockIdx.y * 128, (size_t)be * DD * CHUNK);
    }
}

__global__ __launch_bounds__(256) void qproj_mma_kernel(const float* __restrict__ bq) {
    int be = blockIdx.z;
    int cnt = g_cnt[be];
    int m0 = blockIdx.y * 128;
    if (m0 >= cnt) return;
    int e = be % EE;
    gemm_body<3>(g_Qc, be * NN + m0,
                 g_Wt_h[0], e * DD + blockIdx.x * 128,
                 cnt - m0, bq + e * DD, blockIdx.x * 128,
                 nullptr, g_Qph, g_Qpl, be * NN + m0, 0);
}

__global__ __launch_bounds__(256) void oproj_mma_kernel(const float* __restrict__ bo) {
    int be = blockIdx.z;
    int cnt = g_cnt[be];
    int m0 = blockIdx.y * 128;
    if (m0 >= cnt) return;
    int e = be % EE;
    gemm_body<0>(g_Ac, be * NN + m0,
                 g_Wt_h[3], e * DD + blockIdx.x * 128,
                 cnt - m0, bo + e * DD, blockIdx.x * 128,
                 g_Go, nullptr, nullptr, be * NN + m0, 0);
}

// ------------------------- HMMA flash attention -------------------------------
// QK: 2-term (Q hi+lo x K fp16). PV: P hi x V hi (1-term).
__global__ __launch_bounds__(256, 1) void attn_mma_kernel() {
    extern __shared__ __align__(128) char smb[];
    int h = blockIdx.x, qt = blockIdx.y, be = blockIdx.z;
    int cnt = g_cnt[be];
    int q0 = qt * AQ;
    if (q0 >= cnt) return;
    int nq = min(AQ, cnt - q0);
    int b = be / EE, e = be % EE;
    int tid = threadIdx.x, lane = tid & 31, warp = tid >> 5;
    int wr = warp * 16;

    uint32_t sQ = smem_u32p(smb);
    uint32_t sK0 = sQ + 2 * QPL;          // 2 stages x 1 plane
    uint32_t sV0 = sK0 + 2 * QPL;

    size_t kbase = (size_t)(b * MM + e * CHUNK) * DD + h * HDIM;
    size_t vbase = ((size_t)be * DD + h * HDIM) * CHUNK;

    auto load_kv = [&](int ktile, int stg) {
        uint32_t sKs = sK0 + stg * QPL;
        uint32_t sVs = sV0 + stg * VPL;
#pragma unroll
        for (int i = 0; i < 4; i++) {
            int cid = tid + 256 * i;
            int krow = cid >> 3, kc = (cid & 7) * 8;
            uint32_t kd = (uint32_t)(krow * QSTR + kc) * 2;
            size_t ks = kbase + (size_t)(ktile * 128 + krow) * DD + kc;
            cp_async16(sKs + kd, g_Kb + ks);
            int vrow = cid >> 4, vc = (cid & 15) * 8;
            uint32_t vd = (uint32_t)(vrow * VSTR + vc) * 2;
            size_t vs = vbase + (size_t)vrow * CHUNK + ktile * 128 + vc;
            cp_async16(sVs + vd, g_Vth + vs);
        }
    };

#pragma unroll
    for (int i = 0; i < 4; i++) {
        int cid = tid + 256 * i;
        int row = cid >> 3, c8 = (cid & 7) * 8;
        int gr = be * NN + q0 + min(row, nq - 1);
        uint32_t d = (uint32_t)(row * QSTR + c8) * 2;
        cp_async16(sQ + d, g_Qph + (size_t)gr * DD + h * HDIM + c8);
        cp_async16(sQ + QPL + d, g_Qpl + (size_t)gr * DD + h * HDIM + c8);
    }
    load_kv(0, 0);
    cp_commit();

    float oacc[8][4];
#pragma unroll
    for (int a = 0; a < 8; a++)
#pragma unroll
        for (int r = 0; r < 4; r++) oacc[a][r] = 0.f;
    float run_mx0 = -1e30f, run_mx1 = -1e30f, run_s0 = 0.f, run_s1 = 0.f;

    for (int kt = 0; kt < CHUNK / 128; kt++) {
        int stg = kt & 1;
        if (kt + 1 < CHUNK / 128) {
            load_kv(kt + 1, stg ^ 1);
            cp_commit();
            cp_wait_group<1>();
        } else {
            cp_wait_group<0>();
        }
        __syncthreads();
        uint32_t sKs = sK0 + stg * QPL;
        uint32_t sVs = sV0 + stg * VPL;

        // ---- S = Q K^T (2-term: Qh*K + Ql*K) ----
        float sacc[16][4];
#pragma unroll
        for (int a = 0; a < 16; a++)
#pragma unroll
            for (int r = 0; r < 4; r++) sacc[a][r] = 0.f;

#pragma unroll
        for (int k16 = 0; k16 < 4; k16++) {
            uint32_t aH[4], aL[4];
            uint32_t aaddr = sQ + (uint32_t)((wr + ((lane >> 3) & 1) * 8 + (lane & 7)) * QSTR
                                             + k16 * 16 + (lane >> 4) * 8) * 2;
            ldsm4(aH, aaddr);
            ldsm4(aL, aaddr + QPL);
#pragma unroll
            for (int g = 0; g < 8; g++) {
                uint32_t baddr = sKs + (uint32_t)((g * 16 + (lane >> 4) * 8 + (lane & 7)) * QSTR
                                                  + k16 * 16 + ((lane >> 3) & 1) * 8) * 2;
                uint32_t tH[4];
                ldsm4(tH, baddr);
                mma_f16(sacc[2 * g], aH, tH);
                mma_f16(sacc[2 * g], aL, tH);
                mma_f16(sacc[2 * g + 1], aH, tH + 2);
                mma_f16(sacc[2 * g + 1], aL, tH + 2);
            }
        }

        // ---- online softmax ----
        float mx0 = -1e30f, mx1 = -1e30f;
#pragma unroll
        for (int a = 0; a < 16; a++) {
            mx0 = fmaxf(mx0, fmaxf(sacc[a][0], sacc[a][1]));
            mx1 = fmaxf(mx1, fmaxf(sacc[a][2], sacc[a][3]));
        }
        mx0 = fmaxf(mx0, __shfl_xor_sync(0xffffffffu, mx0, 1));
        mx0 = fmaxf(mx0, __shfl_xor_sync(0xffffffffu, mx0, 2));
        mx1 = fmaxf(mx1, __shfl_xor_sync(0xffffffffu, mx1, 1));
        mx1 = fmaxf(mx1, __shfl_xor_sync(0xffffffffu, mx1, 2));
        float nm0 = fmaxf(run_mx0, mx0), nm1 = fmaxf(run_mx1, mx1);
        float f0 = __expf(run_mx0 - nm0), f1 = __expf(run_mx1 - nm1);
        run_mx0 = nm0; run_mx1 = nm1;
        float s0 = 0.f, s1 = 0.f;
#pragma unroll
        for (int a = 0; a < 16; a++) {
            sacc[a][0] = __expf(sacc[a][0] - nm0); s0 += sacc[a][0];
            sacc[a][1] = __expf(sacc[a][1] - nm0); s0 += sacc[a][1];
            sacc[a][2] = __expf(sacc[a][2] - nm1); s1 += sacc[a][2];
            sacc[a][3] = __expf(sacc[a][3] - nm1); s1 += sacc[a][3];
        }
        s0 += __shfl_xor_sync(0xffffffffu, s0, 1);
        s0 += __shfl_xor_sync(0xffffffffu, s0, 2);
        s1 += __shfl_xor_sync(0xffffffffu, s1, 1);
        s1 += __shfl_xor_sync(0xffffffffu, s1, 2);
        run_s0 = run_s0 * f0 + s0;
        run_s1 = run_s1 * f1 + s1;
#pragma unroll
        for (int a = 0; a < 8; a++) {
            oacc[a][0] *= f0; oacc[a][1] *= f0;
            oacc[a][2] *= f1; oacc[a][3] *= f1;
        }

        // ---- O += P V ----
#pragma unroll
        for (int j = 0; j < 8; j++) {
            uint32_t pH[4];
            pH[0] = pack_h(sacc[2 * j][0], sacc[2 * j][1]);
            pH[1] = pack_h(sacc[2 * j][2], sacc[2 * j][3]);
            pH[2] = pack_h(sacc[2 * j + 1][0], sacc[2 * j + 1][1]);
            pH[3] = pack_h(sacc[2 * j + 1][2], sacc[2 * j + 1][3]);
#pragma unroll
            for (int g = 0; g < 4; g++) {
                uint32_t baddr = sVs + (uint32_t)((g * 16 + (lane >> 4) * 8 + (lane & 7)) * VSTR
                                                  + j * 16 + ((lane >> 3) & 1) * 8) * 2;
                uint32_t tH[4];
                ldsm4(tH, baddr);
                mma_f16(oacc[2 * g], pH, tH);
                mma_f16(oacc[2 * g + 1], pH, tH + 2);
            }
        }
        __syncthreads();
    }

    float inv0 = 1.f / run_s0, inv1 = 1.f / run_s1;
    int r0 = wr + (lane >> 2);
    int cql = (lane & 3) * 2;
#pragma unroll
    for (int a = 0; a < 8; a++) {
        int colg = h * HDIM + a * 8 + cql;
        if (r0 < nq) {
            uint32_t hi = pack_h(oacc[a][0] * inv0, oacc[a][1] * inv0);
            size_t idx = ((size_t)(be * NN + q0 + r0) * DD + colg) >> 1;
            reinterpret_cast<uint32_t*>(g_Ac)[idx] = hi;
        }
        if (r0 + 8 < nq) {
            uint32_t hi = pack_h(oacc[a][2] * inv1, oacc[a][3] * inv1);
            size_t idx = ((size_t)(be * NN + q0 + r0 + 8) * DD + colg) >> 1;
            reinterpret_cast<uint32_t*>(g_Ac)[idx] = hi;
        }
    }
}

// ------------------------- final combine -------------------------------------
__global__ void combine_kernel(float* __restrict__ out) {
    int t = blockIdx.x * blockDim.x + threadIdx.x;
    int qid = t >> 8;
    int d4 = (t & 255) * 4;
    float w0 = g_w[qid * 2 + 0], w1 = g_w[qid * 2 + 1];
    int s0 = g_slot[qid * 2 + 0], s1 = g_slot[qid * 2 + 1];
    float4 a = *reinterpret_cast<const float4*>(g_Go + (size_t)s0 * DD + d4);
    float4 c = *reinterpret_cast<const float4*>(g_Go + (size_t)s1 * DD + d4);
    float4 o;
    o.x = w0 * a.x + w1 * c.x;
    o.y = w0 * a.y + w1 * c.y;
    o.z = w0 * a.z + w1 * c.z;
    o.w = w0 * a.w + w1 * c.w;
    *reinterpret_cast<float4*>(out + (size_t)qid * DD + d4) = o;
}

// ------------------------- launch --------------------------------------------
extern "C" void kernel_launch(void* const* d_in, const int* in_sizes, int n_in,
                              void* d_out, int out_size) {
    const float* queries = (const float*)d_in[0];
    const float* keys    = (const float*)d_in[1];
    const float* values  = (const float*)d_in[2];
    const float* Wq = (const float*)d_in[3];
    const float* bq = (const float*)d_in[4];
    const float* Wk = (const float*)d_in[5];
    const float* bk = (const float*)d_in[6];
    const float* Wv = (const float*)d_in[7];
    const float* bv = (const float*)d_in[8];
    const float* Wo = (const float*)d_in[9];
    const float* bo = (const float*)d_in[10];
    const float* Wr = (const float*)d_in[11];
    const float* br = (const float*)d_in[12];
    float* out = (float*)d_out;
    (void)in_sizes; (void)n_in; (void)out_size;

    cudaFuncSetAttribute(kvproj_mma_kernel, cudaFuncAttributeMaxDynamicSharedMemorySize, GEMM_SMEM);
    cudaFuncSetAttribute(qproj_mma_kernel, cudaFuncAttributeMaxDynamicSharedMemorySize, GEMM_SMEM);
    cudaFuncSetAttribute(oproj_mma_kernel, cudaFuncAttributeMaxDynamicSharedMemorySize, GEMM_SMEM);
    cudaFuncSetAttribute(attn_mma_kernel, cudaFuncAttributeMaxDynamicSharedMemorySize, ATTN_SMEM);

    zero_cnt_kernel<<<1, 32>>>();
    router_kernel<<<(BB * NN) / 8, 256>>>(queries, Wr, br);
    conv_w_kernel<<<dim3(16, 32, 32), 256>>>(Wq, Wk, Wv, Wo);
    conv_kv_kernel<<<(2 * BB * MM * DD / 4) / 256, 256>>>(keys, values);
    gather_split_kernel<<<dim3(NN / 2, BB * EE), 256>>>(queries);
    kvproj_mma_kernel<<<dim3(8, 4, BB * EE * 2), 256, GEMM_SMEM>>>(bk, bv);
    qproj_mma_kernel<<<dim3(8, 16, BB * EE), 256, GEMM_SMEM>>>(bq);
    attn_mma_kernel<<<dim3(HH, NN / AQ, BB * EE), 256, ATTN_SMEM>>>();
    oproj_mma_kernel<<<dim3(8, 16, BB * EE), 256, GEMM_SMEM>>>(bo);
    combine_kernel<<<(BB * NN * DD / 4) / 256, 256>>>(out);
}

// round 13
// speedup vs baseline: 2.2684x; 1.0843x over previous
#include <cuda_runtime.h>
#include <cuda_fp16.h>
#include <cstdint>

#define BB 2
#define NN 2048
#define MM 4096
#define DD 1024
#define HH 16
#define EE 8
#define TK 2
#define HDIM 64
#define CHUNK 512
#define SCALE2 0.1803368801111204f   // 0.125 * log2(e)
#define SLOTS (BB * EE * NN)

#define TKK 32
#define NKT (DD / TKK)
#define ASTR 40
#define PLANE_BYTES (128 * ASTR * 2)
#define STAGE_BYTES (2 * PLANE_BYTES)
#define GEMM_SMEM   (2 * STAGE_BYTES)

// attention tiles: Q 1 plane, K/V double-buffered single planes
#define AQ 128
#define QSTR 72
#define VSTR 136
#define QPL (128 * QSTR * 2)
#define VPL (64 * VSTR * 2)
#define ATTN_SMEM (3 * QPL + 2 * VPL)   // 88 KB

// ------------------------- scratch -------------------------------------------
__device__ float g_Go[(size_t)SLOTS * DD];
__device__ float g_w[BB * NN * TK];
__device__ int   g_slot[BB * NN * TK];
__device__ int   g_qlist[BB * EE * NN];
__device__ int   g_cnt[BB * EE];
__device__ __half g_Kin[(size_t)BB * MM * DD];
__device__ __half g_Vin[(size_t)BB * MM * DD];
__device__ __half g_Qc[(size_t)SLOTS * DD];
__device__ __half g_Ac[(size_t)SLOTS * DD];
__device__ __half g_Kb[(size_t)BB * MM * DD];
__device__ __half g_Vth[(size_t)BB * EE * DD * CHUNK];   // [be][d][key]
__device__ __half g_Qp[(size_t)SLOTS * DD];              // Q proj, pre-scaled by SCALE2
__device__ __half g_Wt_h[4][(size_t)EE * DD * DD];

// ------------------------- PTX helpers ---------------------------------------
__device__ __forceinline__ uint32_t smem_u32p(const void* p) {
    return (uint32_t)__cvta_generic_to_shared(p);
}
__device__ __forceinline__ void cp_async16(uint32_t dst, const void* src) {
    asm volatile("cp.async.cg.shared.global [%0], [%1], 16;\n" :: "r"(dst), "l"(src));
}
__device__ __forceinline__ void cp_commit() {
    asm volatile("cp.async.commit_group;\n" ::: "memory");
}
__device__ __forceinline__ void cp_wait_all() {
    asm volatile("cp.async.wait_group 0;\n" ::: "memory");
}
template <int N>
__device__ __forceinline__ void cp_wait_group() {
    asm volatile("cp.async.wait_group %0;\n" :: "n"(N) : "memory");
}
__device__ __forceinline__ void ldsm4(uint32_t* r, uint32_t addr) {
    asm volatile("ldmatrix.sync.aligned.m8n8.x4.shared.b16 {%0,%1,%2,%3}, [%4];"
                 : "=r"(r[0]), "=r"(r[1]), "=r"(r[2]), "=r"(r[3]) : "r"(addr));
}
__device__ __forceinline__ void mma_f16(float* d, const uint32_t* a, const uint32_t* b) {
    asm volatile(
        "mma.sync.aligned.m16n8k16.row.col.f32.f16.f16.f32 "
        "{%0,%1,%2,%3}, {%4,%5,%6,%7}, {%8,%9}, {%0,%1,%2,%3};"
        : "+f"(d[0]), "+f"(d[1]), "+f"(d[2]), "+f"(d[3])
        : "r"(a[0]), "r"(a[1]), "r"(a[2]), "r"(a[3]), "r"(b[0]), "r"(b[1]));
}
__device__ __forceinline__ uint32_t pack_h(float x, float y) {
    __half2 h2 = __floats2half2_rn(x, y);
    return *reinterpret_cast<uint32_t*>(&h2);
}

// ------------------------- small kernels -------------------------------------
__global__ void zero_cnt_kernel() {
    if (threadIdx.x < BB * EE) g_cnt[threadIdx.x] = 0;
}

__global__ void router_kernel(const float* __restrict__ q,
                              const float* __restrict__ Wr,
                              const float* __restrict__ br) {
    int lane = threadIdx.x & 31;
    int qid = blockIdx.x * (blockDim.x >> 5) + (threadIdx.x >> 5);
    if (qid >= BB * NN) return;
    const float* qrow = q + (size_t)qid * DD;
    float acc[EE];
#pragma unroll
    for (int e = 0; e < EE; e++) acc[e] = 0.f;
    for (int d = lane; d < DD; d += 32) {
        float qv = qrow[d];
        const float4* w4 = reinterpret_cast<const float4*>(Wr + d * EE);
        float4 w0 = w4[0], w1 = w4[1];
        acc[0] += qv * w0.x; acc[1] += qv * w0.y;
        acc[2] += qv * w0.z; acc[3] += qv * w0.w;
        acc[4] += qv * w1.x; acc[5] += qv * w1.y;
        acc[6] += qv * w1.z; acc[7] += qv * w1.w;
    }
#pragma unroll
    for (int e = 0; e < EE; e++) {
#pragma unroll
        for (int o = 16; o > 0; o >>= 1)
            acc[e] += __shfl_xor_sync(0xffffffffu, acc[e], o);
    }
    if (lane == 0) {
        float v[EE];
#pragma unroll
        for (int e = 0; e < EE; e++) v[e] = acc[e] + br[e];
        int i0 = 0;
#pragma unroll
        for (int e = 1; e < EE; e++) if (v[e] > v[i0]) i0 = e;
        int i1 = (i0 == 0) ? 1 : 0;
#pragma unroll
        for (int e = 0; e < EE; e++) if (e != i0 && v[e] > v[i1]) i1 = e;
        float ex = __expf(v[i1] - v[i0]);
        float inv = 1.f / (1.f + ex);
        g_w[qid * 2 + 0] = inv;
        g_w[qid * 2 + 1] = ex * inv;
        int b = qid / NN, n = qid % NN;
        int be0 = b * EE + i0;
        int p0 = atomicAdd(&g_cnt[be0], 1);
        g_qlist[be0 * NN + p0] = n;
        g_slot[qid * 2 + 0] = be0 * NN + p0;
        int be1 = b * EE + i1;
        int p1 = atomicAdd(&g_cnt[be1], 1);
        g_qlist[be1 * NN + p1] = n;
        g_slot[qid * 2 + 1] = be1 * NN + p1;
    }
}

// ------------------------- converts ------------------------------------------
__global__ void conv_w_kernel(const float* __restrict__ Wq, const float* __restrict__ Wk,
                              const float* __restrict__ Wv, const float* __restrict__ Wo) {
    __shared__ float sm[64][33];
    int w = blockIdx.z >> 3, e = blockIdx.z & 7;
    const float* src = (w == 0 ? Wq : w == 1 ? Wk : w == 2 ? Wv : Wo) + (size_t)e * DD * DD;
    int k0 = blockIdx.x * 64, n0 = blockIdx.y * 32;
    int tid = threadIdx.x, rr = tid >> 5, cc = tid & 31;
#pragma unroll
    for (int i = 0; i < 8; i++)
        sm[rr + 8 * i][cc] = src[(size_t)(k0 + rr + 8 * i) * DD + n0 + cc];
    __syncthreads();
    __half* dh = g_Wt_h[w] + (size_t)e * DD * DD;
    int lane = tid & 31, wrow = tid >> 5;
#pragma unroll
    for (int j = 0; j < 4; j++) {
        int n = wrow + 8 * j;
        uint32_t h2 = pack_h(sm[lane * 2 + 0][n], sm[lane * 2 + 1][n]);
        size_t o = ((size_t)(n0 + n) * DD + k0 + lane * 2) >> 1;
        reinterpret_cast<uint32_t*>(dh)[o] = h2;
    }
}

__global__ void conv_kv_kernel(const float* __restrict__ keys,
                               const float* __restrict__ values) {
    size_t n4 = (size_t)BB * MM * DD / 4;
    size_t t = (size_t)blockIdx.x * blockDim.x + threadIdx.x;
    int which = (t >= n4);
    size_t i4 = which ? (t - n4) : t;
    float4 v = reinterpret_cast<const float4*>(which ? values : keys)[i4];
    uint32_t h[2];
    h[0] = pack_h(v.x, v.y);
    h[1] = pack_h(v.z, v.w);
    __half* dh = which ? g_Vin : g_Kin;
    reinterpret_cast<uint2*>(dh)[i4] = *reinterpret_cast<uint2*>(h);
}

__global__ void gather_split_kernel(const float* __restrict__ queries) {
    int be = blockIdx.y;
    int p = blockIdx.x * 2 + (threadIdx.x >> 7);
    if (p >= g_cnt[be]) return;
    int l128 = threadIdx.x & 127;
    int slot = be * NN + p;
    int b = be / EE;
    int n = g_qlist[be * NN + p];
    const float* src = queries + ((size_t)b * NN + n) * DD + l128 * 8;
    float4 v0 = *reinterpret_cast<const float4*>(src);
    float4 v1 = *reinterpret_cast<const float4*>(src + 4);
    uint32_t h[4];
    h[0] = pack_h(v0.x, v0.y);
    h[1] = pack_h(v0.z, v0.w);
    h[2] = pack_h(v1.x, v1.y);
    h[3] = pack_h(v1.z, v1.w);
    __half* dh = g_Qc + (size_t)slot * DD + l128 * 8;
    *reinterpret_cast<uint4*>(dh) = *reinterpret_cast<const uint4*>(h);
}

// ------------------------- HMMA fp16 GEMM core --------------------------------
// MODE 0: fp32 out. 1: fp16 plane [row][DD]. 2: V-transposed plane.
// 3: fp16 plane [row][DD] scaled by SCALE2.
template <int MODE>
__device__ __forceinline__ void gemm_body(
    const __half* __restrict__ Ah, int rowA0,
    const __half* __restrict__ Bh, int rowB0,
    int climit, const float* __restrict__ bias, int n0,
    float* __restrict__ C, __half* __restrict__ Ph,
    long crow0, size_t vtb)
{
    extern __shared__ __align__(128) char smx[];
    int tid = threadIdx.x, lane = tid & 31, warp = tid >> 5;
    uint32_t sm0 = smem_u32p(smx);

    int row0 = tid >> 2, col0 = (tid & 3) * 8;
    const __half* gsrc[2];
    gsrc[0] = Ah + (size_t)(rowA0 + row0) * DD + col0;
    gsrc[1] = Bh + (size_t)(rowB0 + row0) * DD + col0;
    uint32_t soff0 = (uint32_t)(row0 * ASTR + col0) * 2;
    uint32_t soff1 = soff0 + 64 * ASTR * 2;

    int wr = (warp >> 2) * 64, wc = (warp & 3) * 32;
    uint32_t aRow = (uint32_t)(wr + ((lane >> 3) & 1) * 8 + (lane & 7));
    uint32_t aCol = (uint32_t)((lane >> 4) * 8);
    uint32_t bRow = (uint32_t)(wc + (lane >> 4) * 8 + (lane & 7));
    uint32_t bCol = (uint32_t)(((lane >> 3) & 1) * 8);

    float acc[4][4][4];
#pragma unroll
    for (int i = 0; i < 4; i++)
#pragma unroll
        for (int j = 0; j < 4; j++)
#pragma unroll
            for (int r = 0; r < 4; r++) acc[i][j][r] = 0.f;

    {
        uint32_t base = sm0;
#pragma unroll
        for (int p = 0; p < 2; p++) {
            cp_async16(base + p * PLANE_BYTES + soff0, gsrc[p]);
            cp_async16(base + p * PLANE_BYTES + soff1, gsrc[p] + (size_t)64 * DD);
        }
        cp_commit();
    }

    for (int kt = 0; kt < NKT; kt++) {
        int st = kt & 1;
        cp_wait_all();
        __syncthreads();
        if (kt + 1 < NKT) {
            uint32_t base = sm0 + (st ^ 1) * STAGE_BYTES;
            int k0 = (kt + 1) * TKK;
#pragma unroll
            for (int p = 0; p < 2; p++) {
                cp_async16(base + p * PLANE_BYTES + soff0, gsrc[p] + k0);
                cp_async16(base + p * PLANE_BYTES + soff1, gsrc[p] + (size_t)64 * DD + k0);
            }
            cp_commit();
        }
        uint32_t base = sm0 + st * STAGE_BYTES;
#pragma unroll
        for (int k16 = 0; k16 < 2; k16++) {
            uint32_t ah[4][4], bh[4][2];
#pragma unroll
            for (int ma = 0; ma < 4; ma++) {
                uint32_t addr = base + ((aRow + ma * 16) * ASTR + k16 * 16 + aCol) * 2;
                ldsm4(ah[ma], addr);
            }
#pragma unroll
            for (int g = 0; g < 2; g++) {
                uint32_t addr = base + PLANE_BYTES
                              + ((bRow + g * 16) * ASTR + k16 * 16 + bCol) * 2;
                uint32_t t4[4];
                ldsm4(t4, addr);
                bh[2 * g][0] = t4[0]; bh[2 * g][1] = t4[1];
                bh[2 * g + 1][0] = t4[2]; bh[2 * g + 1][1] = t4[3];
            }
#pragma unroll
            for (int ma = 0; ma < 4; ma++)
#pragma unroll
                for (int na = 0; na < 4; na++)
                    mma_f16(acc[ma][na], ah[ma], bh[na]);
        }
    }

    int rql = lane >> 2, cql = (lane & 3) * 2;
#pragma unroll
    for (int na = 0; na < 4; na++) {
        int colg = n0 + wc + na * 8 + cql;
        float b0 = bias[colg], b1 = bias[colg + 1];
#pragma unroll
        for (int ma = 0; ma < 4; ma++) {
#pragma unroll
            for (int hh = 0; hh < 2; hh++) {
                int rowt = wr + ma * 16 + rql + hh * 8;
                if (rowt >= climit) continue;
                float v0 = acc[ma][na][hh * 2 + 0] + b0;
                float v1 = acc[ma][na][hh * 2 + 1] + b1;
                if (MODE == 0) {
                    *reinterpret_cast<float2*>(C + (size_t)(crow0 + rowt) * DD + colg) =
                        make_float2(v0, v1);
                } else if (MODE == 1 || MODE == 3) {
                    if (MODE == 3) { v0 *= SCALE2; v1 *= SCALE2; }
                    size_t idx = ((size_t)(crow0 + rowt) * DD + colg) >> 1;
                    reinterpret_cast<uint32_t*>(Ph)[idx] = pack_h(v0, v1);
                } else {  // MODE 2: transposed V
                    size_t key = (size_t)(crow0 + rowt);
                    Ph[vtb + (size_t)colg * CHUNK + key] = __float2half_rn(v0);
                    Ph[vtb + (size_t)(colg + 1) * CHUNK + key] = __float2half_rn(v1);
                }
            }
        }
    }
}

__global__ __launch_bounds__(256) void kvproj_mma_kernel(
    const float* __restrict__ bk, const float* __restrict__ bv) {
    int z = blockIdx.z;
    int which = z & 1, be = z >> 1;
    int b = be / EE, e = be % EE;
    int rowA0 = b * MM + e * CHUNK + blockIdx.y * 128;
    if (which == 0) {
        gemm_body<1>(g_Kin, rowA0,
                     g_Wt_h[1], e * DD + blockIdx.x * 128,
                     128, bk + e * DD, blockIdx.x * 128,
                     nullptr, g_Kb, rowA0, 0);
    } else {
        gemm_body<2>(g_Vin, rowA0,
                     g_Wt_h[2], e * DD + blockIdx.x * 128,
                     128, bv + e * DD, blockIdx.x * 128,
                     nullptr, g_Vth, blockIdx.y * 128, (size_t)be * DD * CHUNK);
    }
}

__global__ __launch_bounds__(256) void qproj_mma_kernel(const float* __restrict__ bq) {
    int be = blockIdx.z;
    int cnt = g_cnt[be];
    int m0 = blockIdx.y * 128;
    if (m0 >= cnt) return;
    int e = be % EE;
    gemm_body<3>(g_Qc, be * NN + m0,
                 g_Wt_h[0], e * DD + blockIdx.x * 128,
                 cnt - m0, bq + e * DD, blockIdx.x * 128,
                 nullptr, g_Qp, be * NN + m0, 0);
}

__global__ __launch_bounds__(256) void oproj_mma_kernel(const float* __restrict__ bo) {
    int be = blockIdx.z;
    int cnt = g_cnt[be];
    int m0 = blockIdx.y * 128;
    if (m0 >= cnt) return;
    int e = be % EE;
    gemm_body<0>(g_Ac, be * NN + m0,
                 g_Wt_h[3], e * DD + blockIdx.x * 128,
                 cnt - m0, bo + e * DD, blockIdx.x * 128,
                 g_Go, nullptr, be * NN + m0, 0);
}

// ------------------------- HMMA flash attention -------------------------------
// QK: 1-term (Q fp16, pre-scaled by 0.125*log2e). PV: 1-term. exp2f softmax.
__global__ __launch_bounds__(256, 2) void attn_mma_kernel() {
    extern __shared__ __align__(128) char smb[];
    int h = blockIdx.x, qt = blockIdx.y, be = blockIdx.z;
    int cnt = g_cnt[be];
    int q0 = qt * AQ;
    if (q0 >= cnt) return;
    int nq = min(AQ, cnt - q0);
    int b = be / EE, e = be % EE;
    int tid = threadIdx.x, lane = tid & 31, warp = tid >> 5;
    int wr = warp * 16;

    uint32_t sQ = smem_u32p(smb);
    uint32_t sK0 = sQ + QPL;              // 2 stages x 1 plane
    uint32_t sV0 = sK0 + 2 * QPL;

    size_t kbase = (size_t)(b * MM + e * CHUNK) * DD + h * HDIM;
    size_t vbase = ((size_t)be * DD + h * HDIM) * CHUNK;

    auto load_kv = [&](int ktile, int stg) {
        uint32_t sKs = sK0 + stg * QPL;
        uint32_t sVs = sV0 + stg * VPL;
#pragma unroll
        for (int i = 0; i < 4; i++) {
            int cid = tid + 256 * i;
            int krow = cid >> 3, kc = (cid & 7) * 8;
            uint32_t kd = (uint32_t)(krow * QSTR + kc) * 2;
            size_t ks = kbase + (size_t)(ktile * 128 + krow) * DD + kc;
            cp_async16(sKs + kd, g_Kb + ks);
            int vrow = cid >> 4, vc = (cid & 15) * 8;
            uint32_t vd = (uint32_t)(vrow * VSTR + vc) * 2;
            size_t vs = vbase + (size_t)vrow * CHUNK + ktile * 128 + vc;
            cp_async16(sVs + vd, g_Vth + vs);
        }
    };

    // Q tile: 128 rows x 8 chunks = 1024 chunks over 256 threads
#pragma unroll
    for (int i = 0; i < 4; i++) {
        int cid = tid + 256 * i;
        int row = cid >> 3, c8 = (cid & 7) * 8;
        int gr = be * NN + q0 + min(row, nq - 1);
        uint32_t d = (uint32_t)(row * QSTR + c8) * 2;
        cp_async16(sQ + d, g_Qp + (size_t)gr * DD + h * HDIM + c8);
    }
    load_kv(0, 0);
    cp_commit();

    float oacc[8][4];
#pragma unroll
    for (int a = 0; a < 8; a++)
#pragma unroll
        for (int r = 0; r < 4; r++) oacc[a][r] = 0.f;
    float run_mx0 = -1e30f, run_mx1 = -1e30f, run_s0 = 0.f, run_s1 = 0.f;

    for (int kt = 0; kt < CHUNK / 128; kt++) {
        int stg = kt & 1;
        if (kt + 1 < CHUNK / 128) {
            load_kv(kt + 1, stg ^ 1);
            cp_commit();
            cp_wait_group<1>();
        } else {
            cp_wait_group<0>();
        }
        __syncthreads();
        uint32_t sKs = sK0 + stg * QPL;
        uint32_t sVs = sV0 + stg * VPL;

        // ---- S = Q K^T (1-term; logits already in log2 scale) ----
        float sacc[16][4];
#pragma unroll
        for (int a = 0; a < 16; a++)
#pragma unroll
            for (int r = 0; r < 4; r++) sacc[a][r] = 0.f;

#pragma unroll
        for (int k16 = 0; k16 < 4; k16++) {
            uint32_t aH[4];
            uint32_t aaddr = sQ + (uint32_t)((wr + ((lane >> 3) & 1) * 8 + (lane & 7)) * QSTR
                                             + k16 * 16 + (lane >> 4) * 8) * 2;
            ldsm4(aH, aaddr);
#pragma unroll
            for (int g = 0; g < 8; g++) {
                uint32_t baddr = sKs + (uint32_t)((g * 16 + (lane >> 4) * 8 + (lane & 7)) * QSTR
                                                  + k16 * 16 + ((lane >> 3) & 1) * 8) * 2;
                uint32_t tH[4];
                ldsm4(tH, baddr);
                mma_f16(sacc[2 * g], aH, tH);
                mma_f16(sacc[2 * g + 1], aH, tH + 2);
            }
        }

        // ---- online softmax (base-2) ----
        float mx0 = -1e30f, mx1 = -1e30f;
#pragma unroll
        for (int a = 0; a < 16; a++) {
            mx0 = fmaxf(mx0, fmaxf(sacc[a][0], sacc[a][1]));
            mx1 = fmaxf(mx1, fmaxf(sacc[a][2], sacc[a][3]));
        }
        mx0 = fmaxf(mx0, __shfl_xor_sync(0xffffffffu, mx0, 1));
        mx0 = fmaxf(mx0, __shfl_xor_sync(0xffffffffu, mx0, 2));
        mx1 = fmaxf(mx1, __shfl_xor_sync(0xffffffffu, mx1, 1));
        mx1 = fmaxf(mx1, __shfl_xor_sync(0xffffffffu, mx1, 2));
        float nm0 = fmaxf(run_mx0, mx0), nm1 = fmaxf(run_mx1, mx1);
        float f0 = exp2f(run_mx0 - nm0), f1 = exp2f(run_mx1 - nm1);
        run_mx0 = nm0; run_mx1 = nm1;
        float s0 = 0.f, s1 = 0.f;
#pragma unroll
        for (int a = 0; a < 16; a++) {
            sacc[a][0] = exp2f(sacc[a][0] - nm0); s0 += sacc[a][0];
            sacc[a][1] = exp2f(sacc[a][1] - nm0); s0 += sacc[a][1];
            sacc[a][2] = exp2f(sacc[a][2] - nm1); s1 += sacc[a][2];
            sacc[a][3] = exp2f(sacc[a][3] - nm1); s1 += sacc[a][3];
        }
        s0 += __shfl_xor_sync(0xffffffffu, s0, 1);
        s0 += __shfl_xor_sync(0xffffffffu, s0, 2);
        s1 += __shfl_xor_sync(0xffffffffu, s1, 1);
        s1 += __shfl_xor_sync(0xffffffffu, s1, 2);
        run_s0 = run_s0 * f0 + s0;
        run_s1 = run_s1 * f1 + s1;
#pragma unroll
        for (int a = 0; a < 8; a++) {
            oacc[a][0] *= f0; oacc[a][1] *= f0;
            oacc[a][2] *= f1; oacc[a][3] *= f1;
        }

        // ---- O += P V ----
#pragma unroll
        for (int j = 0; j < 8; j++) {
            uint32_t pH[4];
            pH[0] = pack_h(sacc[2 * j][0], sacc[2 * j][1]);
            pH[1] = pack_h(sacc[2 * j][2], sacc[2 * j][3]);
            pH[2] = pack_h(sacc[2 * j + 1][0], sacc[2 * j + 1][1]);
            pH[3] = pack_h(sacc[2 * j + 1][2], sacc[2 * j + 1][3]);
#pragma unroll
            for (int g = 0; g < 4; g++) {
                uint32_t baddr = sVs + (uint32_t)((g * 16 + (lane >> 4) * 8 + (lane & 7)) * VSTR
                                                  + j * 16 + ((lane >> 3) & 1) * 8) * 2;
                uint32_t tH[4];
                ldsm4(tH, baddr);
                mma_f16(oacc[2 * g], pH, tH);
                mma_f16(oacc[2 * g + 1], pH, tH + 2);
            }
        }
        __syncthreads();
    }

    float inv0 = 1.f / run_s0, inv1 = 1.f / run_s1;
    int r0 = wr + (lane >> 2);
    int cql = (lane & 3) * 2;
#pragma unroll
    for (int a = 0; a < 8; a++) {
        int colg = h * HDIM + a * 8 + cql;
        if (r0 < nq) {
            uint32_t hi = pack_h(oacc[a][0] * inv0, oacc[a][1] * inv0);
            size_t idx = ((size_t)(be * NN + q0 + r0) * DD + colg) >> 1;
            reinterpret_cast<uint32_t*>(g_Ac)[idx] = hi;
        }
        if (r0 + 8 < nq) {
            uint32_t hi = pack_h(oacc[a][2] * inv1, oacc[a][3] * inv1);
            size_t idx = ((size_t)(be * NN + q0 + r0 + 8) * DD + colg) >> 1;
            reinterpret_cast<uint32_t*>(g_Ac)[idx] = hi;
        }
    }
}

// ------------------------- final combine -------------------------------------
__global__ void combine_kernel(float* __restrict__ out) {
    int t = blockIdx.x * blockDim.x + threadIdx.x;
    int qid = t >> 8;
    int d4 = (t & 255) * 4;
    float w0 = g_w[qid * 2 + 0], w1 = g_w[qid * 2 + 1];
    int s0 = g_slot[qid * 2 + 0], s1 = g_slot[qid * 2 + 1];
    float4 a = *reinterpret_cast<const float4*>(g_Go + (size_t)s0 * DD + d4);
    float4 c = *reinterpret_cast<const float4*>(g_Go + (size_t)s1 * DD + d4);
    float4 o;
    o.x = w0 * a.x + w1 * c.x;
    o.y = w0 * a.y + w1 * c.y;
    o.z = w0 * a.z + w1 * c.z;
    o.w = w0 * a.w + w1 * c.w;
    *reinterpret_cast<float4*>(out + (size_t)qid * DD + d4) = o;
}

// ------------------------- launch --------------------------------------------
extern "C" void kernel_launch(void* const* d_in, const int* in_sizes, int n_in,
                              void* d_out, int out_size) {
    const float* queries = (const float*)d_in[0];
    const float* keys    = (const float*)d_in[1];
    const float* values  = (const float*)d_in[2];
    const float* Wq = (const float*)d_in[3];
    const float* bq = (const float*)d_in[4];
    const float* Wk = (const float*)d_in[5];
    const float* bk = (const float*)d_in[6];
    const float* Wv = (const float*)d_in[7];
    const float* bv = (const float*)d_in[8];
    const float* Wo = (const float*)d_in[9];
    const float* bo = (const float*)d_in[10];
    const float* Wr = (const float*)d_in[11];
    const float* br = (const float*)d_in[12];
    float* out = (float*)d_out;
    (void)in_sizes; (void)n_in; (void)out_size;

    cudaFuncSetAttribute(kvproj_mma_kernel, cudaFuncAttributeMaxDynamicSharedMemorySize, GEMM_SMEM);
    cudaFuncSetAttribute(qproj_mma_kernel, cudaFuncAttributeMaxDynamicSharedMemorySize, GEMM_SMEM);
    cudaFuncSetAttribute(oproj_mma_kernel, cudaFuncAttributeMaxDynamicSharedMemorySize, GEMM_SMEM);
    cudaFuncSetAttribute(attn_mma_kernel, cudaFuncAttributeMaxDynamicSharedMemorySize, ATTN_SMEM);

    zero_cnt_kernel<<<1, 32>>>();
    router_kernel<<<(BB * NN) / 8, 256>>>(queries, Wr, br);
    conv_w_kernel<<<dim3(16, 32, 32), 256>>>(Wq, Wk, Wv, Wo);
    conv_kv_kernel<<<(2 * BB * MM * DD / 4) / 256, 256>>>(keys, values);
    gather_split_kernel<<<dim3(NN / 2, BB * EE), 256>>>(queries);
    kvproj_mma_kernel<<<dim3(8, 4, BB * EE * 2), 256, GEMM_SMEM>>>(bk, bv);
    qproj_mma_kernel<<<dim3(8, 16, BB * EE), 256, GEMM_SMEM>>>(bq);
    attn_mma_kernel<<<dim3(HH, NN / AQ, BB * EE), 256, ATTN_SMEM>>>();
    oproj_mma_kernel<<<dim3(8, 16, BB * EE), 256, GEMM_SMEM>>>(bo);
    combine_kernel<<<(BB * NN * DD / 4) / 256, 256>>>(out);
}